// round 13
// baseline (speedup 1.0000x reference)
#include <cuda_runtime.h>
#include <cuda_bf16.h>
#include <math.h>
#include <stdint.h>

#define BB 2
#define SS 2048
#define DD 528
#define HH 16
#define FF 16
#define EE 33            // HEAD_DIM = 2*FF+1
#define MTOT (BB*SS)     // 4096
#define WIN 64

#define KP1 1600         // padded 3*528
#define KP2 3200         // padded 3*1056
#define KC  1056         // concat K for output GEMM
#define NP_D  576        // 528 padded to 64 multiple
#define NWIN 1728        // 3*576 concat win projection width
#define NLIN 1040        // 256+256+528 concat lin projection width

// ---------------- scratch (device globals; no allocations allowed) -------------
static __device__ __align__(128) float g_qkv_lin[MTOT*NLIN];   // [q(256)|k(256)|v(528)]
static __device__ __align__(128) float g_qkv_win[MTOT*NWIN];   // [q(576)|k(576)|v(576)]
static __device__ __align__(128) float g_wlinb[DD*NLIN];
static __device__ __align__(128) float g_kv[BB*HH*EE*EE];
static __device__ __align__(128) float g_ksum[BB*HH*EE];

// bf16 split operands
static __device__ __align__(128) __nv_bfloat16 g_xb [MTOT*KP1];
static __device__ __align__(128) __nv_bfloat16 g_ob [MTOT*KP2];   // padding cols stay 0
static __device__ __align__(128) __nv_bfloat16 g_wwinb[NWIN*KP1]; // [Wq|Wk|Wv]_win split
static __device__ __align__(128) __nv_bfloat16 g_wob [NP_D*KP2];

// ==================== helpers =================================================
__device__ __forceinline__ uint32_t smem_to_u32(const void* p) {
    uint32_t a;
    asm("{ .reg .u64 t; cvta.to.shared.u64 t, %1; cvt.u32.u64 %0, t; }" : "=r"(a) : "l"(p));
    return a;
}
#define LDSM_X4(r0, r1, r2, r3, addr) \
    asm volatile("ldmatrix.sync.aligned.m8n8.x4.shared.b16 {%0,%1,%2,%3}, [%4];" \
        : "=r"(r0), "=r"(r1), "=r"(r2), "=r"(r3) : "r"(addr))
#define MMA_BF16(c0, c1, c2, c3, a0, a1, a2, a3, b0, b1) \
    asm volatile("mma.sync.aligned.m16n8k16.row.col.f32.bf16.bf16.f32 " \
        "{%0,%1,%2,%3}, {%4,%5,%6,%7}, {%8,%9}, {%0,%1,%2,%3};" \
        : "+f"(c0), "+f"(c1), "+f"(c2), "+f"(c3) \
        : "r"(a0), "r"(a1), "r"(a2), "r"(a3), "r"(b0), "r"(b1))
#define MMA_TF32(c, a0, a1, a2, a3, b0, b1) \
    asm volatile("mma.sync.aligned.m16n8k8.row.col.f32.tf32.tf32.f32 " \
        "{%0,%1,%2,%3}, {%4,%5,%6,%7}, {%8,%9}, {%0,%1,%2,%3};" \
        : "+f"((c)[0]), "+f"((c)[1]), "+f"((c)[2]), "+f"((c)[3]) \
        : "r"(a0), "r"(a1), "r"(a2), "r"(a3), "r"(b0), "r"(b1))
__device__ __forceinline__ float to_tf32(float v) {
    uint32_t u; asm("cvt.rna.tf32.f32 %0, %1;" : "=r"(u) : "f"(v));
    return __uint_as_float(u);
}
__device__ __forceinline__ void store_ob3(size_t base, int col, float v) {
    __nv_bfloat16 hi = __float2bfloat16(v);
    __nv_bfloat16 lo = __float2bfloat16(v - __bfloat162float(hi));
    g_ob[base + col]          = hi;
    g_ob[base + KC + col]     = lo;
    g_ob[base + 2 * KC + col] = hi;
}
// pair-interleave permutation: (kc*8 + t + 4j) -> kc*8 + 2t + j
__device__ __forceinline__ int permc(int c) {
    return (c & ~7) | ((c & 3) << 1) | ((c >> 2) & 1);
}

// ==================== conversion / concat kernels =============================
__global__ void split_x_kernel(const float* __restrict__ x)
{
    int idx = blockIdx.x * blockDim.x + threadIdx.x;
    if (idx >= MTOT * KP1) return;
    int k = idx % KP1, m = idx / KP1;
    __nv_bfloat16 o;
    if (k < DD)            o = __float2bfloat16(x[m*DD + k]);
    else if (k < 2*DD) { float f = x[m*DD + k - DD]; __nv_bfloat16 h = __float2bfloat16(f);
                         o = __float2bfloat16(f - __bfloat162float(h)); }
    else if (k < 3*DD)     o = __float2bfloat16(x[m*DD + k - 2*DD]);
    else                   o = __float2bfloat16(0.f);
    g_xb[idx] = o;
}

__global__ void split_wwin_kernel(const float* __restrict__ Wq, const float* __restrict__ Wk,
                                  const float* __restrict__ Wv)
{
    int idx = blockIdx.x * blockDim.x + threadIdx.x;
    if (idx >= NWIN * KP1) return;
    int n = idx / KP1, k = idx % KP1;
    int sel = n / NP_D, nn = n - sel * NP_D;
    __nv_bfloat16 o = __float2bfloat16(0.f);
    if (nn < DD && k < 3*DD) {
        int k0 = (k < DD) ? k : ((k < 2*DD) ? k - DD : k - 2*DD);
        const float* W = (sel == 0) ? Wq : ((sel == 1) ? Wk : Wv);
        float f = W[(size_t)k0 * DD + nn];
        __nv_bfloat16 h = __float2bfloat16(f);
        o = (k < 2*DD) ? h : __float2bfloat16(f - __bfloat162float(h));
    }
    g_wwinb[idx] = o;
}

__global__ void split_wo_kernel(const float* __restrict__ Wol, const float* __restrict__ Wow)
{
    int idx = blockIdx.x * blockDim.x + threadIdx.x;
    if (idx >= NP_D * KP2) return;
    int n = idx / KP2, k = idx % KP2;
    __nv_bfloat16 o = __float2bfloat16(0.f);
    if (n < DD && k < 3*KC) {
        int k0 = k % KC;
        float f = (k0 < DD) ? Wol[(size_t)k0 * DD + n] : Wow[(size_t)(k0 - DD) * DD + n];
        __nv_bfloat16 h = __float2bfloat16(f);
        o = (k < 2*KC) ? h : __float2bfloat16(f - __bfloat162float(h));
    }
    g_wob[idx] = o;
}

__global__ void concat_wlin_kernel(const float* __restrict__ Wq, const float* __restrict__ Wk,
                                   const float* __restrict__ Wv)
{
    int idx = blockIdx.x * blockDim.x + threadIdx.x;
    if (idx >= DD * NLIN) return;
    int k = idx / NLIN, n = idx % NLIN;
    float v;
    if (n < 256)      v = Wq[(size_t)k * 256 + n];
    else if (n < 512) v = Wk[(size_t)k * 256 + n - 256];
    else              v = Wv[(size_t)k * DD  + n - 512];
    g_wlinb[idx] = v;
}

// ==================== fp32 SIMT GEMM (lin path), 128x128 tile, 8x8 micro ======
#define LM 128
#define LN 128
#define LK 16

__global__ void __launch_bounds__(256)
gemm_lin_kernel(const float* __restrict__ A, const float* __restrict__ B,
                float* __restrict__ C, int M, int N, int K)
{
    __shared__ float As[LK][LM];
    __shared__ float Bs[LK][LN + 4];

    int tid = threadIdx.x;
    int tx = tid & 15, ty = tid >> 4;
    int bm = blockIdx.y * LM, bn = blockIdx.x * LN;

    float c[8][8];
#pragma unroll
    for (int i = 0; i < 8; i++)
#pragma unroll
        for (int j = 0; j < 8; j++) c[i][j] = 0.f;

    int ra = tid & 127, ka = (tid >> 7) * 8;
    int kb = tid >> 4, cb = (tid & 15) * 4;

    const float* Ag = A + (size_t)(bm + ra) * K + ka;
    const float* Bg = B + (size_t)kb * N + bn;
    bool ok0 = (bn + cb) < N;
    bool ok1 = (bn + 64 + cb) < N;

    const int T = K / LK;
    float4 va0, va1, vb0, vb1;
    va0 = *(const float4*)(Ag);
    va1 = *(const float4*)(Ag + 4);
    vb0 = ok0 ? *(const float4*)(Bg + cb)      : make_float4(0.f, 0.f, 0.f, 0.f);
    vb1 = ok1 ? *(const float4*)(Bg + 64 + cb) : make_float4(0.f, 0.f, 0.f, 0.f);

    for (int t = 0; t < T; t++) {
        As[ka + 0][ra] = va0.x; As[ka + 1][ra] = va0.y;
        As[ka + 2][ra] = va0.z; As[ka + 3][ra] = va0.w;
        As[ka + 4][ra] = va1.x; As[ka + 5][ra] = va1.y;
        As[ka + 6][ra] = va1.z; As[ka + 7][ra] = va1.w;
        *(float4*)&Bs[kb][cb]      = vb0;
        *(float4*)&Bs[kb][64 + cb] = vb1;
        __syncthreads();

        if (t + 1 < T) {
            int k0 = (t + 1) * LK;
            va0 = *(const float4*)(Ag + k0);
            va1 = *(const float4*)(Ag + k0 + 4);
            const float* Bt = Bg + (size_t)k0 * N;
            vb0 = ok0 ? *(const float4*)(Bt + cb)      : make_float4(0.f, 0.f, 0.f, 0.f);
            vb1 = ok1 ? *(const float4*)(Bt + 64 + cb) : make_float4(0.f, 0.f, 0.f, 0.f);
        }

#pragma unroll
        for (int k = 0; k < LK; k++) {
            float a[8], b[8];
            *(float4*)&a[0] = *(const float4*)&As[k][ty * 4];
            *(float4*)&a[4] = *(const float4*)&As[k][64 + ty * 4];
            *(float4*)&b[0] = *(const float4*)&Bs[k][tx * 4];
            *(float4*)&b[4] = *(const float4*)&Bs[k][64 + tx * 4];
#pragma unroll
            for (int i = 0; i < 8; i++)
#pragma unroll
                for (int j = 0; j < 8; j++) c[i][j] += a[i] * b[j];
        }
        __syncthreads();
    }

#pragma unroll
    for (int ih = 0; ih < 2; ih++)
#pragma unroll
    for (int i = 0; i < 4; i++) {
        int row = bm + ih * 64 + ty * 4 + i;
        float* Crow = C + (size_t)row * N;
#pragma unroll
        for (int jh = 0; jh < 2; jh++) {
            int col = bn + jh * 64 + tx * 4;
            if (col < N) {
                *(float4*)(Crow + col) = make_float4(c[ih*4+i][jh*4+0], c[ih*4+i][jh*4+1],
                                                     c[ih*4+i][jh*4+2], c[ih*4+i][jh*4+3]);
            }
        }
    }
}

// ==================== HMMA (mma.sync) bf16 GEMM ===============================
#define SROW 40

__global__ void __launch_bounds__(256)
gemm_mma_kernel(const __nv_bfloat16* __restrict__ A, const __nv_bfloat16* __restrict__ B,
                float* __restrict__ C, int Kp, int Nact)
{
    __shared__ __align__(16) __nv_bfloat16 sA[2][128 * SROW];
    __shared__ __align__(16) __nv_bfloat16 sB[2][64 * SROW];

    int tid  = threadIdx.x;
    int wid  = tid >> 5, lane = tid & 31;
    int wm   = (wid >> 1) * 32;
    int wn   = (wid & 1) * 32;
    int bm   = blockIdx.y * 128;
    int bn   = blockIdx.x * 64;

    const __nv_bfloat16* Ab = A + (size_t)bm * Kp;
    const __nv_bfloat16* Bb = B + (size_t)bn * Kp;

    uint32_t uA = smem_to_u32(sA);
    uint32_t uB = smem_to_u32(sB);

    int a_row = wm + (lane & 15);
    int a_ke  = (lane >> 4) * 8;
    int b_row = wn + (lane & 7) + ((lane >> 4) << 3);
    int b_ke  = ((lane >> 3) & 1) * 8;

    float c[2][4][4];
#pragma unroll
    for (int mi = 0; mi < 2; mi++)
#pragma unroll
        for (int ni = 0; ni < 4; ni++)
#pragma unroll
            for (int r = 0; r < 4; r++) c[mi][ni][r] = 0.f;

    const int T = Kp >> 5;

    int arA0 = (tid      ) >> 2, acA0 = (tid      ) & 3;
    int arA1 = (tid + 256) >> 2, acA1 = (tid + 256) & 3;
    int arB  = tid >> 2,         acB  = tid & 3;

    {
        uint4 va0 = *(const uint4*)(Ab + (size_t)arA0 * Kp + acA0 * 8);
        uint4 va1 = *(const uint4*)(Ab + (size_t)arA1 * Kp + acA1 * 8);
        uint4 vb  = *(const uint4*)(Bb + (size_t)arB  * Kp + acB  * 8);
        *(uint4*)(&sA[0][arA0 * SROW + acA0 * 8]) = va0;
        *(uint4*)(&sA[0][arA1 * SROW + acA1 * 8]) = va1;
        *(uint4*)(&sB[0][arB  * SROW + acB  * 8]) = vb;
    }
    __syncthreads();

    for (int t = 0; t < T; t++) {
        int s = t & 1;
        uint4 va0, va1, vb;
        if (t + 1 < T) {
            int k0 = (t + 1) << 5;
            va0 = *(const uint4*)(Ab + (size_t)arA0 * Kp + k0 + acA0 * 8);
            va1 = *(const uint4*)(Ab + (size_t)arA1 * Kp + k0 + acA1 * 8);
            vb  = *(const uint4*)(Bb + (size_t)arB  * Kp + k0 + acB  * 8);
        }

        uint32_t baseA = uA + (uint32_t)(s * 128 * SROW * 2);
        uint32_t baseB = uB + (uint32_t)(s * 64 * SROW * 2);
#pragma unroll
        for (int kk = 0; kk < 2; kk++) {
            uint32_t a0[4], a1[4], b0[4], b1[4];
            LDSM_X4(a0[0], a0[1], a0[2], a0[3],
                    baseA + (uint32_t)(((a_row      ) * SROW + kk * 16 + a_ke) * 2));
            LDSM_X4(a1[0], a1[1], a1[2], a1[3],
                    baseA + (uint32_t)(((a_row + 16 ) * SROW + kk * 16 + a_ke) * 2));
            LDSM_X4(b0[0], b0[1], b0[2], b0[3],
                    baseB + (uint32_t)(((b_row      ) * SROW + kk * 16 + b_ke) * 2));
            LDSM_X4(b1[0], b1[1], b1[2], b1[3],
                    baseB + (uint32_t)(((b_row + 16 ) * SROW + kk * 16 + b_ke) * 2));
#pragma unroll
            for (int mi = 0; mi < 2; mi++) {
                uint32_t* aa = mi ? a1 : a0;
                MMA_BF16(c[mi][0][0], c[mi][0][1], c[mi][0][2], c[mi][0][3],
                         aa[0], aa[1], aa[2], aa[3], b0[0], b0[1]);
                MMA_BF16(c[mi][1][0], c[mi][1][1], c[mi][1][2], c[mi][1][3],
                         aa[0], aa[1], aa[2], aa[3], b0[2], b0[3]);
                MMA_BF16(c[mi][2][0], c[mi][2][1], c[mi][2][2], c[mi][2][3],
                         aa[0], aa[1], aa[2], aa[3], b1[0], b1[1]);
                MMA_BF16(c[mi][3][0], c[mi][3][1], c[mi][3][2], c[mi][3][3],
                         aa[0], aa[1], aa[2], aa[3], b1[2], b1[3]);
            }
        }

        if (t + 1 < T) {
            int ns = (t + 1) & 1;
            *(uint4*)(&sA[ns][arA0 * SROW + acA0 * 8]) = va0;
            *(uint4*)(&sA[ns][arA1 * SROW + acA1 * 8]) = va1;
            *(uint4*)(&sB[ns][arB  * SROW + acB  * 8]) = vb;
        }
        __syncthreads();
    }

#pragma unroll
    for (int mi = 0; mi < 2; mi++) {
        int r0 = bm + wm + mi * 16 + (lane >> 2);
#pragma unroll
        for (int ni = 0; ni < 4; ni++) {
            int col = bn + wn + ni * 8 + (lane & 3) * 2;
            if (col < Nact) {
                *(float2*)(C + (size_t)r0 * Nact + col) =
                    make_float2(c[mi][ni][0], c[mi][ni][1]);
                *(float2*)(C + (size_t)(r0 + 8) * Nact + col) =
                    make_float2(c[mi][ni][2], c[mi][ni][3]);
            }
        }
    }
}

// ==================== linear attention ========================================
__global__ void clear_kv_kernel()
{
    int i = blockIdx.x * blockDim.x + threadIdx.x;
    if (i < BB * HH * EE * EE) g_kv[i] = 0.f;
    if (i < BB * HH * EE)      g_ksum[i] = 0.f;
}

#define KV_SEGS 16
__global__ void lin_kv_kernel()
{
    int bh  = blockIdx.x;
    int seg = blockIdx.y;
    int b = bh >> 4, h = bh & 15;
    int n0base = seg * (SS / KV_SEGS);

    __shared__ float sk[64][FF];
    __shared__ float sv[64][EE];

    int tid = threadIdx.x;
    const int NITEMS = EE * EE + EE;

    float acc[5];
    int   di[5], ei[5];
    int cnt = 0;
    for (int it = tid; it < NITEMS; it += 256) {
        acc[cnt] = 0.f;
        if (it < EE * EE) { di[cnt] = it / EE; ei[cnt] = it % EE; }
        else              { di[cnt] = it - EE * EE; ei[cnt] = -1; }
        cnt++;
    }

    for (int c0 = 0; c0 < SS / KV_SEGS; c0 += 64) {
        int n0 = n0base + c0;
        {
            int r = tid >> 2, f = (tid & 3) * 4;
            const float4 k4 = *(const float4*)(g_qkv_lin + ((size_t)(b * SS + n0 + r)) * NLIN + 256 + h * FF + f);
            sk[r][f + 0] = k4.x; sk[r][f + 1] = k4.y; sk[r][f + 2] = k4.z; sk[r][f + 3] = k4.w;
        }
        for (int i = tid; i < 64 * EE; i += 256) {
            int r = i / EE, e = i % EE;
            sv[r][e] = g_qkv_lin[((size_t)(b * SS + n0 + r)) * NLIN + 512 + h * EE + e];
        }
        __syncthreads();

        for (int u = 0; u < cnt; u++) {
            int d = di[u], e = ei[u];
            float a = acc[u];
            if (e >= 0) {
                if (d == 0) {
                    for (int nn = 0; nn < 64; nn++) a += sv[nn][e];
                } else if (d <= FF) {
                    int dd = d - 1;
                    for (int nn = 0; nn < 64; nn++) a += sk[nn][dd] * sv[nn][e];
                } else {
                    int dd = d - 1 - FF;
                    for (int nn = 0; nn < 64; nn++) { float kk = sk[nn][dd]; a += 0.5f * kk * kk * sv[nn][e]; }
                }
            } else {
                if (d == 0) {
                    a += 64.f;
                } else if (d <= FF) {
                    int dd = d - 1;
                    for (int nn = 0; nn < 64; nn++) a += sk[nn][dd];
                } else {
                    int dd = d - 1 - FF;
                    for (int nn = 0; nn < 64; nn++) { float kk = sk[nn][dd]; a += 0.5f * kk * kk; }
                }
            }
            acc[u] = a;
        }
        __syncthreads();
    }

    for (int u = 0; u < cnt; u++) {
        if (ei[u] >= 0) atomicAdd(&g_kv[((size_t)bh) * EE * EE + di[u] * EE + ei[u]], acc[u]);
        else            atomicAdd(&g_ksum[bh * EE + di[u]], acc[u]);
    }
}

// writes its result directly into g_ob concat columns [0, 528)
__global__ void lin_out_kernel(const int* __restrict__ mask)
{
    int s = blockIdx.x, b = blockIdx.y;
    __shared__ float sq[HH * FF];
    int tid = threadIdx.x;
    if (tid < HH * FF) sq[tid] = g_qkv_lin[((size_t)(b * SS + s)) * NLIN + tid];
    __syncthreads();
    if (tid >= DD) return;

    int h = tid / EE, e = tid % EE;
    const float* kv = g_kv + ((size_t)(b * HH + h)) * EE * EE;
    const float* q  = sq + h * FF;

    float qkv  = kv[e];
    float qsum = 1.f;
#pragma unroll
    for (int j = 0; j < FF; j++) {
        float qa = q[j];
        float q2 = 0.5f * qa * qa;
        qkv  += qa * kv[(1 + j) * EE + e] + q2 * kv[(1 + FF + j) * EE + e];
        qsum += qa + q2;
    }
    float z = qsum * g_ksum[(b * HH + h) * EE + e];
    float out = qkv / (z + 1e-9f);
    if (mask[b * SS + s] == 0) out = 0.f;
    store_ob3((size_t)(b * SS + s) * KP2, tid, out);
}

// ==================== tf32 MMA flash window attention =========================
// Double-buffered + interleaved K/V layouts (LDS.64 fragment loads), ballot
// mask bitmask with full-tile fast path, warp-local softmax in place.
// smem floats: sS 128*68 (8704) | sK2 2*64*40 (5120) | sV2 2*40*72 (5760) | 4 mask words
#define WM_SMEM (19600*4)

__global__ void __launch_bounds__(256)
win_mma_kernel(const int* __restrict__ mask)
{
    extern __shared__ float smf[];
    float* sS = smf;                    // 128*68
    unsigned* maskw = (unsigned*)(smf + 19584);

    int qt = (int)gridDim.x - 1 - (int)blockIdx.x;
    int bh = blockIdx.y; int b = bh >> 4, h = bh & 15;
    int tid = threadIdx.x, wid = tid >> 5, lane = tid & 31;
    int g = lane >> 2, t = lane & 3;
    int rw = wid * 16;
    int q0 = qt * 128;
    int kend = min(SS, q0 + 127 + WIN);
    const float scale = 0.17407765595569785f;   // 1/sqrt(33)

    // stage Q (pre-scaled, tf32) into sS; extract A fragments once
    for (int i = tid; i < 128 * 40; i += 256) {
        int r = i / 40, d = i - r * 40;
        float v = (d < EE) ? g_qkv_win[((size_t)(b * SS + q0 + r)) * NWIN + h * EE + d] * scale : 0.f;
        sS[r * 68 + d] = to_tf32(v);
    }
    __syncthreads();
    uint32_t aq[5][4];
#pragma unroll
    for (int kc = 0; kc < 5; kc++) {
        aq[kc][0] = __float_as_uint(sS[(rw + g    ) * 68 + kc * 8 + t    ]);
        aq[kc][1] = __float_as_uint(sS[(rw + g + 8) * 68 + kc * 8 + t    ]);
        aq[kc][2] = __float_as_uint(sS[(rw + g    ) * 68 + kc * 8 + t + 4]);
        aq[kc][3] = __float_as_uint(sS[(rw + g + 8) * 68 + kc * 8 + t + 4]);
    }
    __syncthreads();

    float co[5][4];
#pragma unroll
    for (int n = 0; n < 5; n++)
#pragma unroll
        for (int r = 0; r < 4; r++) co[n][r] = 0.f;
    float mrun0 = -1e30f, mrun1 = -1e30f, lsum0 = 0.f, lsum1 = 0.f;

    const int T = (kend + 63) >> 6;
    float kr_[10], vr_[10]; int mk_;

    // prologue: load tile 0 into regs, stage into buffer 0
    {
        int nv = min(64, kend);
#pragma unroll
        for (int j = 0; j < 10; j++) {
            int i = tid + j * 256;
            int r = i / 40, d = i - r * 40;
            bool ok = (r < nv) && (d < EE);
            size_t rowb = ((size_t)(b * SS + r)) * NWIN;
            kr_[j] = ok ? g_qkv_win[rowb + 576 + h * EE + d] : 0.f;
            vr_[j] = ok ? g_qkv_win[rowb + 1152 + h * EE + d] : 0.f;
        }
        mk_ = (tid < 64) ? ((tid < nv) ? mask[b * SS + tid] : 0) : 0;
#pragma unroll
        for (int j = 0; j < 10; j++) {
            int i = tid + j * 256;
            int r = i / 40, d = i - r * 40;
            smf[8704 + r * 40 + permc(d)] = to_tf32(kr_[j]);
            smf[13824 + d * 72 + (permc(r) ^ (((d >> 2) & 7) << 1))] = to_tf32(vr_[j]);
        }
        if (wid < 2) {
            unsigned bal = __ballot_sync(0xffffffffu, mk_ != 0);
            if (lane == 0) maskw[wid] = bal;
        }
    }
    __syncthreads();

    for (int tt = 0; tt < T; tt++) {
        int buf = tt & 1;
        int kt = tt << 6;
        float* sK2 = smf + 8704  + buf * 2560;
        float* sV2 = smf + 13824 + buf * 2880;
        uint64_t mbits = ((uint64_t)maskw[buf * 2 + 1] << 32) | maskw[buf * 2];

        // prefetch tile tt+1 into registers
        if (tt + 1 < T) {
            int ktn = (tt + 1) << 6;
            int nv = min(64, kend - ktn);
#pragma unroll
            for (int j = 0; j < 10; j++) {
                int i = tid + j * 256;
                int r = i / 40, d = i - r * 40;
                bool ok = (r < nv) && (d < EE);
                size_t rowb = ((size_t)(b * SS + ktn + r)) * NWIN;
                kr_[j] = ok ? g_qkv_win[rowb + 576 + h * EE + d] : 0.f;
                vr_[j] = ok ? g_qkv_win[rowb + 1152 + h * EE + d] : 0.f;
            }
            mk_ = (tid < 64) ? ((tid < nv) ? mask[b * SS + ktn + tid] : 0) : 0;
        }

        // --- QK^T: S[16 x 64] per warp (interleaved K, LDS.64 frags) ---
        float cs[8][4];
#pragma unroll
        for (int n = 0; n < 8; n++)
#pragma unroll
            for (int r = 0; r < 4; r++) cs[n][r] = 0.f;
#pragma unroll
        for (int kc = 0; kc < 5; kc++)
#pragma unroll
            for (int n = 0; n < 8; n++) {
                float2 kb = *(float2*)&sK2[(n * 8 + g) * 40 + kc * 8 + 2 * t];
                MMA_TF32(cs[n], aq[kc][0], aq[kc][1], aq[kc][2], aq[kc][3],
                         __float_as_uint(kb.x), __float_as_uint(kb.y));
            }

        // --- mask IN PLACE (fast path for full tiles) ---
        if (!(mbits == ~0ull && kt <= q0)) {
            int r0g = q0 + rw + g, r1g = r0g + 8;
#pragma unroll
            for (int n = 0; n < 8; n++) {
                int c0 = n * 8 + 2 * t;
                int cg0 = kt + c0, cg1 = cg0 + 1;
                bool m0 = (mbits >> c0) & 1, m1 = (mbits >> (c0 + 1)) & 1;
                if (!(m0 && cg0 <= r0g + WIN - 1)) cs[n][0] = -1e30f;
                if (!(m1 && cg1 <= r0g + WIN - 1)) cs[n][1] = -1e30f;
                if (!(m0 && cg0 <= r1g + WIN - 1)) cs[n][2] = -1e30f;
                if (!(m1 && cg1 <= r1g + WIN - 1)) cs[n][3] = -1e30f;
            }
        }

        // --- warp-local online softmax, exp IN PLACE ---
        float mx0 = -1e30f, mx1 = -1e30f;
#pragma unroll
        for (int n = 0; n < 8; n++) {
            mx0 = fmaxf(mx0, fmaxf(cs[n][0], cs[n][1]));
            mx1 = fmaxf(mx1, fmaxf(cs[n][2], cs[n][3]));
        }
        mx0 = fmaxf(mx0, __shfl_xor_sync(0xffffffffu, mx0, 1));
        mx0 = fmaxf(mx0, __shfl_xor_sync(0xffffffffu, mx0, 2));
        mx1 = fmaxf(mx1, __shfl_xor_sync(0xffffffffu, mx1, 1));
        mx1 = fmaxf(mx1, __shfl_xor_sync(0xffffffffu, mx1, 2));
        float mn0 = fmaxf(mrun0, mx0), mn1 = fmaxf(mrun1, mx1);
        float fac0 = __expf(mrun0 - mn0), fac1 = __expf(mrun1 - mn1);
        float ps0 = 0.f, ps1 = 0.f;
#pragma unroll
        for (int n = 0; n < 8; n++) {
            cs[n][0] = __expf(cs[n][0] - mn0); ps0 += cs[n][0];
            cs[n][1] = __expf(cs[n][1] - mn0); ps0 += cs[n][1];
            cs[n][2] = __expf(cs[n][2] - mn1); ps1 += cs[n][2];
            cs[n][3] = __expf(cs[n][3] - mn1); ps1 += cs[n][3];
        }
        ps0 += __shfl_xor_sync(0xffffffffu, ps0, 1);
        ps0 += __shfl_xor_sync(0xffffffffu, ps0, 2);
        ps1 += __shfl_xor_sync(0xffffffffu, ps1, 1);
        ps1 += __shfl_xor_sync(0xffffffffu, ps1, 2);
        lsum0 = lsum0 * fac0 + ps0; mrun0 = mn0;
        lsum1 = lsum1 * fac1 + ps1; mrun1 = mn1;

        // --- stage P (tf32) into own rows of sS (warp-local) ---
#pragma unroll
        for (int n = 0; n < 8; n++) {
            int c0 = n * 8 + 2 * t;
            *(float2*)&sS[(rw + g    ) * 68 + c0] = make_float2(to_tf32(cs[n][0]), to_tf32(cs[n][1]));
            *(float2*)&sS[(rw + g + 8) * 68 + c0] = make_float2(to_tf32(cs[n][2]), to_tf32(cs[n][3]));
        }
        __syncwarp();

        // --- rescale + P @ V (interleaved V, LDS.64 frags) ---
#pragma unroll
        for (int n = 0; n < 5; n++) {
            co[n][0] *= fac0; co[n][1] *= fac0; co[n][2] *= fac1; co[n][3] *= fac1;
        }
#pragma unroll
        for (int kc = 0; kc < 8; kc++) {
            uint32_t a0 = __float_as_uint(sS[(rw + g    ) * 68 + kc * 8 + t    ]);
            uint32_t a1 = __float_as_uint(sS[(rw + g + 8) * 68 + kc * 8 + t    ]);
            uint32_t a2 = __float_as_uint(sS[(rw + g    ) * 68 + kc * 8 + t + 4]);
            uint32_t a3 = __float_as_uint(sS[(rw + g + 8) * 68 + kc * 8 + t + 4]);
#pragma unroll
            for (int n = 0; n < 5; n++) {
                int vrow = n * 8 + g;
                int vcol = (kc * 8 + 2 * t) ^ (((vrow >> 2) & 7) << 1);
                float2 vb = *(float2*)&sV2[vrow * 72 + vcol];
                MMA_TF32(co[n], a0, a1, a2, a3,
                         __float_as_uint(vb.x), __float_as_uint(vb.y));
            }
        }

        // --- store prefetched tile into the other buffer ---
        if (tt + 1 < T) {
            int nb = 1 - buf;
            float* nK = smf + 8704  + nb * 2560;
            float* nV = smf + 13824 + nb * 2880;
#pragma unroll
            for (int j = 0; j < 10; j++) {
                int i = tid + j * 256;
                int r = i / 40, d = i - r * 40;
                nK[r * 40 + permc(d)] = to_tf32(kr_[j]);
                nV[d * 72 + (permc(r) ^ (((d >> 2) & 7) << 1))] = to_tf32(vr_[j]);
            }
            if (wid < 2) {
                unsigned bal = __ballot_sync(0xffffffffu, mk_ != 0);
                if (lane == 0) maskw[nb * 2 + wid] = bal;
            }
        }
        __syncthreads();
    }

    float inv0 = 1.f / lsum0, inv1 = 1.f / lsum1;
    int r0 = q0 + rw + g, r1 = r0 + 8;
    size_t base0 = (size_t)(b * SS + r0) * KP2;
    size_t base1 = (size_t)(b * SS + r1) * KP2;
    int colbase = DD + h * EE;
#pragma unroll
    for (int n = 0; n < 5; n++) {
        int c0 = n * 8 + 2 * t;
        if (c0 < EE) {
            store_ob3(base0, colbase + c0, co[n][0] * inv0);
            store_ob3(base1, colbase + c0, co[n][2] * inv1);
        }
        if (c0 + 1 < EE) {
            store_ob3(base0, colbase + c0 + 1, co[n][1] * inv0);
            store_ob3(base1, colbase + c0 + 1, co[n][3] * inv1);
        }
    }
}

// ==================== launcher ================================================
extern "C" void kernel_launch(void* const* d_in, const int* in_sizes, int n_in,
                              void* d_out, int out_size)
{
    const float* x      = (const float*)d_in[0];
    const int*   mask   = (const int*)  d_in[1];
    const float* Wq_lin = (const float*)d_in[2];
    const float* Wk_lin = (const float*)d_in[3];
    const float* Wv_lin = (const float*)d_in[4];
    const float* Wo_lin = (const float*)d_in[5];
    const float* Wq_win = (const float*)d_in[6];
    const float* Wk_win = (const float*)d_in[7];
    const float* Wv_win = (const float*)d_in[8];
    const float* Wo_win = (const float*)d_in[9];
    float* out = (float*)d_out;

    float *p_qkv_lin, *p_qkv_win, *p_wlinb;
    __nv_bfloat16 *p_xb, *p_ob, *p_wwinb, *p_wob;
    cudaGetSymbolAddress((void**)&p_qkv_lin, g_qkv_lin);
    cudaGetSymbolAddress((void**)&p_qkv_win, g_qkv_win);
    cudaGetSymbolAddress((void**)&p_wlinb,   g_wlinb);
    cudaGetSymbolAddress((void**)&p_xb,   g_xb);
    cudaGetSymbolAddress((void**)&p_ob,   g_ob);
    cudaGetSymbolAddress((void**)&p_wwinb, g_wwinb);
    cudaGetSymbolAddress((void**)&p_wob,  g_wob);

    static cudaStream_t s_win = 0;
    static cudaEvent_t  evFork = 0, evJoin = 0;
    if (s_win == 0) {
        cudaStreamCreateWithFlags(&s_win, cudaStreamNonBlocking);
        cudaEventCreateWithFlags(&evFork, cudaEventDisableTiming);
        cudaEventCreateWithFlags(&evJoin, cudaEventDisableTiming);
        cudaFuncSetAttribute(win_mma_kernel, cudaFuncAttributeMaxDynamicSharedMemorySize, WM_SMEM);
    }

    // -------- fork win chain off the capture stream --------
    cudaEventRecord(evFork, 0);
    cudaStreamWaitEvent(s_win, evFork, 0);

    // win chain (s_win): splits -> merged HMMA projection -> tf32 flash attn
    split_x_kernel<<<(MTOT*KP1 + 255)/256, 256, 0, s_win>>>(x);
    split_wwin_kernel<<<(NWIN*KP1 + 255)/256, 256, 0, s_win>>>(Wq_win, Wk_win, Wv_win);
    gemm_mma_kernel<<<dim3(NWIN/64, MTOT/128), 256, 0, s_win>>>(p_xb, p_wwinb, p_qkv_win, KP1, NWIN);
    win_mma_kernel<<<dim3(SS/128, BB*HH), 256, WM_SMEM, s_win>>>(mask);

    // lin chain (capture stream): wo split + merged fp32 projection -> linear attn
    split_wo_kernel<<<(NP_D*KP2 + 255)/256, 256>>>(Wo_lin, Wo_win);
    concat_wlin_kernel<<<(DD*NLIN + 255)/256, 256>>>(Wq_lin, Wk_lin, Wv_lin);
    gemm_lin_kernel<<<dim3((NLIN + LN - 1)/LN, MTOT/LM), 256>>>(x, p_wlinb, p_qkv_lin, MTOT, NLIN, DD);
    clear_kv_kernel<<<(BB*HH*EE*EE + 255)/256, 256>>>();
    lin_kv_kernel<<<dim3(BB*HH, KV_SEGS), 256>>>();
    lin_out_kernel<<<dim3(SS, BB), 544>>>(mask);

    // -------- join, then fused output projection --------
    cudaEventRecord(evJoin, s_win);
    cudaStreamWaitEvent(0, evJoin, 0);
    gemm_mma_kernel<<<dim3(NP_D/64, MTOT/128), 256>>>(p_ob, p_wob, out, KP2, DD);
}

// round 15
// speedup vs baseline: 1.0565x; 1.0565x over previous
#include <cuda_runtime.h>
#include <cuda_bf16.h>
#include <math.h>
#include <stdint.h>

#define BB 2
#define SS 2048
#define DD 528
#define HH 16
#define FF 16
#define EE 33            // HEAD_DIM = 2*FF+1
#define MTOT (BB*SS)     // 4096
#define WIN 64

#define KP1 1600         // padded 3*528
#define KP2 3200         // padded 3*1056
#define KC  1056         // concat K for output GEMM
#define NP_D  576        // 528 padded to 64 multiple
#define NWIN 1728        // 3*576 concat win projection width
#define NLIN 1040        // 256+256+528 concat lin projection width

// ---------------- scratch (device globals; no allocations allowed) -------------
static __device__ __align__(128) float g_qkv_lin[MTOT*NLIN];   // [q(256)|k(256)|v(528)]
static __device__ __align__(128) float g_qkv_win[MTOT*NWIN];   // [q(576)|k(576)|v(576)]
static __device__ __align__(128) float g_wlinb[DD*NLIN];
static __device__ __align__(128) float g_kv[BB*HH*EE*EE];
static __device__ __align__(128) float g_ksum[BB*HH*EE];

// bf16 split operands
static __device__ __align__(128) __nv_bfloat16 g_xb [MTOT*KP1];
static __device__ __align__(128) __nv_bfloat16 g_ob [MTOT*KP2];   // padding cols stay 0
static __device__ __align__(128) __nv_bfloat16 g_wwinb[NWIN*KP1]; // [Wq|Wk|Wv]_win split
static __device__ __align__(128) __nv_bfloat16 g_wob [NP_D*KP2];

// ==================== helpers =================================================
__device__ __forceinline__ uint32_t smem_to_u32(const void* p) {
    uint32_t a;
    asm("{ .reg .u64 t; cvta.to.shared.u64 t, %1; cvt.u32.u64 %0, t; }" : "=r"(a) : "l"(p));
    return a;
}
#define LDSM_X4(r0, r1, r2, r3, addr) \
    asm volatile("ldmatrix.sync.aligned.m8n8.x4.shared.b16 {%0,%1,%2,%3}, [%4];" \
        : "=r"(r0), "=r"(r1), "=r"(r2), "=r"(r3) : "r"(addr))
#define MMA_BF16(c0, c1, c2, c3, a0, a1, a2, a3, b0, b1) \
    asm volatile("mma.sync.aligned.m16n8k16.row.col.f32.bf16.bf16.f32 " \
        "{%0,%1,%2,%3}, {%4,%5,%6,%7}, {%8,%9}, {%0,%1,%2,%3};" \
        : "+f"(c0), "+f"(c1), "+f"(c2), "+f"(c3) \
        : "r"(a0), "r"(a1), "r"(a2), "r"(a3), "r"(b0), "r"(b1))
#define MMA_TF32(c, a0, a1, a2, a3, b0, b1) \
    asm volatile("mma.sync.aligned.m16n8k8.row.col.f32.tf32.tf32.f32 " \
        "{%0,%1,%2,%3}, {%4,%5,%6,%7}, {%8,%9}, {%0,%1,%2,%3};" \
        : "+f"((c)[0]), "+f"((c)[1]), "+f"((c)[2]), "+f"((c)[3]) \
        : "r"(a0), "r"(a1), "r"(a2), "r"(a3), "r"(b0), "r"(b1))
__device__ __forceinline__ float to_tf32(float v) {
    uint32_t u; asm("cvt.rna.tf32.f32 %0, %1;" : "=r"(u) : "f"(v));
    return __uint_as_float(u);
}
__device__ __forceinline__ float ex2f(float x) {
    float r; asm("ex2.approx.ftz.f32 %0, %1;" : "=f"(r) : "f"(x)); return r;
}
__device__ __forceinline__ void store_ob3(size_t base, int col, float v) {
    __nv_bfloat16 hi = __float2bfloat16(v);
    __nv_bfloat16 lo = __float2bfloat16(v - __bfloat162float(hi));
    g_ob[base + col]          = hi;
    g_ob[base + KC + col]     = lo;
    g_ob[base + 2 * KC + col] = hi;
}

// ==================== conversion / concat kernels =============================
__global__ void split_x_kernel(const float* __restrict__ x)
{
    int idx = blockIdx.x * blockDim.x + threadIdx.x;
    if (idx >= MTOT * KP1) return;
    int k = idx % KP1, m = idx / KP1;
    __nv_bfloat16 o;
    if (k < DD)            o = __float2bfloat16(x[m*DD + k]);
    else if (k < 2*DD) { float f = x[m*DD + k - DD]; __nv_bfloat16 h = __float2bfloat16(f);
                         o = __float2bfloat16(f - __bfloat162float(h)); }
    else if (k < 3*DD)     o = __float2bfloat16(x[m*DD + k - 2*DD]);
    else                   o = __float2bfloat16(0.f);
    g_xb[idx] = o;
}

// coalesced win weight split via 32x32 smem transpose. grid (KP1/32, NWIN/32), block (32,8)
__global__ void split_wwin_kernel(const float* __restrict__ Wq, const float* __restrict__ Wk,
                                  const float* __restrict__ Wv)
{
    __shared__ float tile[32][33];
    int kt0 = blockIdx.x * 32, nt0 = blockIdx.y * 32;
    for (int kk = threadIdx.y; kk < 32; kk += 8) {
        int k = kt0 + kk;
        int ng = nt0 + threadIdx.x;
        int sel = ng / NP_D, nn = ng - sel * NP_D;
        float f = 0.f;
        if (k < 3*DD && nn < DD) {
            int k0 = (k < DD) ? k : ((k < 2*DD) ? k - DD : k - 2*DD);
            const float* W = (sel == 0) ? Wq : ((sel == 1) ? Wk : Wv);
            f = W[(size_t)k0 * DD + nn];
        }
        tile[kk][threadIdx.x] = f;
    }
    __syncthreads();
    for (int nn2 = threadIdx.y; nn2 < 32; nn2 += 8) {
        int n = nt0 + nn2;
        int k = kt0 + threadIdx.x;
        float f = tile[threadIdx.x][nn2];
        __nv_bfloat16 h = __float2bfloat16(f);
        __nv_bfloat16 o = (k < 2*DD) ? h : __float2bfloat16(f - __bfloat162float(h));
        g_wwinb[(size_t)n * KP1 + k] = o;
    }
}

// coalesced output-weight split. grid (KP2/32, NP_D/32), block (32,8)
__global__ void split_wo_kernel(const float* __restrict__ Wol, const float* __restrict__ Wow)
{
    __shared__ float tile[32][33];
    int kt0 = blockIdx.x * 32, nt0 = blockIdx.y * 32;
    for (int kk = threadIdx.y; kk < 32; kk += 8) {
        int k = kt0 + kk;
        int n = nt0 + threadIdx.x;
        float f = 0.f;
        if (k < 3*KC && n < DD) {
            int k0 = k % KC;
            f = (k0 < DD) ? Wol[(size_t)k0 * DD + n] : Wow[(size_t)(k0 - DD) * DD + n];
        }
        tile[kk][threadIdx.x] = f;
    }
    __syncthreads();
    for (int nn2 = threadIdx.y; nn2 < 32; nn2 += 8) {
        int n = nt0 + nn2;
        int k = kt0 + threadIdx.x;
        float f = tile[threadIdx.x][nn2];
        __nv_bfloat16 h = __float2bfloat16(f);
        __nv_bfloat16 o = (k < 2*KC) ? h : __float2bfloat16(f - __bfloat162float(h));
        g_wob[(size_t)n * KP2 + k] = o;
    }
}

__global__ void concat_wlin_kernel(const float* __restrict__ Wq, const float* __restrict__ Wk,
                                   const float* __restrict__ Wv)
{
    int idx = blockIdx.x * blockDim.x + threadIdx.x;
    if (idx >= DD * NLIN) return;
    int k = idx / NLIN, n = idx % NLIN;
    float v;
    if (n < 256)      v = Wq[(size_t)k * 256 + n];
    else if (n < 512) v = Wk[(size_t)k * 256 + n - 256];
    else              v = Wv[(size_t)k * DD  + n - 512];
    g_wlinb[idx] = v;
}

// ==================== fp32 SIMT GEMM (lin path), 128x128 tile, 8x8 micro ======
#define LM 128
#define LN 128
#define LK 16

__global__ void __launch_bounds__(256)
gemm_lin_kernel(const float* __restrict__ A, const float* __restrict__ B,
                float* __restrict__ C, int M, int N, int K)
{
    __shared__ float As[LK][LM];
    __shared__ float Bs[LK][LN + 4];

    int tid = threadIdx.x;
    int tx = tid & 15, ty = tid >> 4;
    int bm = blockIdx.y * LM, bn = blockIdx.x * LN;

    float c[8][8];
#pragma unroll
    for (int i = 0; i < 8; i++)
#pragma unroll
        for (int j = 0; j < 8; j++) c[i][j] = 0.f;

    int ra = tid & 127, ka = (tid >> 7) * 8;
    int kb = tid >> 4, cb = (tid & 15) * 4;

    const float* Ag = A + (size_t)(bm + ra) * K + ka;
    const float* Bg = B + (size_t)kb * N + bn;
    bool ok0 = (bn + cb) < N;
    bool ok1 = (bn + 64 + cb) < N;

    const int T = K / LK;
    float4 va0, va1, vb0, vb1;
    va0 = *(const float4*)(Ag);
    va1 = *(const float4*)(Ag + 4);
    vb0 = ok0 ? *(const float4*)(Bg + cb)      : make_float4(0.f, 0.f, 0.f, 0.f);
    vb1 = ok1 ? *(const float4*)(Bg + 64 + cb) : make_float4(0.f, 0.f, 0.f, 0.f);

    for (int t = 0; t < T; t++) {
        As[ka + 0][ra] = va0.x; As[ka + 1][ra] = va0.y;
        As[ka + 2][ra] = va0.z; As[ka + 3][ra] = va0.w;
        As[ka + 4][ra] = va1.x; As[ka + 5][ra] = va1.y;
        As[ka + 6][ra] = va1.z; As[ka + 7][ra] = va1.w;
        *(float4*)&Bs[kb][cb]      = vb0;
        *(float4*)&Bs[kb][64 + cb] = vb1;
        __syncthreads();

        if (t + 1 < T) {
            int k0 = (t + 1) * LK;
            va0 = *(const float4*)(Ag + k0);
            va1 = *(const float4*)(Ag + k0 + 4);
            const float* Bt = Bg + (size_t)k0 * N;
            vb0 = ok0 ? *(const float4*)(Bt + cb)      : make_float4(0.f, 0.f, 0.f, 0.f);
            vb1 = ok1 ? *(const float4*)(Bt + 64 + cb) : make_float4(0.f, 0.f, 0.f, 0.f);
        }

#pragma unroll
        for (int k = 0; k < LK; k++) {
            float a[8], b[8];
            *(float4*)&a[0] = *(const float4*)&As[k][ty * 4];
            *(float4*)&a[4] = *(const float4*)&As[k][64 + ty * 4];
            *(float4*)&b[0] = *(const float4*)&Bs[k][tx * 4];
            *(float4*)&b[4] = *(const float4*)&Bs[k][64 + tx * 4];
#pragma unroll
            for (int i = 0; i < 8; i++)
#pragma unroll
                for (int j = 0; j < 8; j++) c[i][j] += a[i] * b[j];
        }
        __syncthreads();
    }

#pragma unroll
    for (int ih = 0; ih < 2; ih++)
#pragma unroll
    for (int i = 0; i < 4; i++) {
        int row = bm + ih * 64 + ty * 4 + i;
        float* Crow = C + (size_t)row * N;
#pragma unroll
        for (int jh = 0; jh < 2; jh++) {
            int col = bn + jh * 64 + tx * 4;
            if (col < N) {
                *(float4*)(Crow + col) = make_float4(c[ih*4+i][jh*4+0], c[ih*4+i][jh*4+1],
                                                     c[ih*4+i][jh*4+2], c[ih*4+i][jh*4+3]);
            }
        }
    }
}

// ==================== HMMA (mma.sync) bf16 GEMM ===============================
#define SROW 40

__global__ void __launch_bounds__(256)
gemm_mma_kernel(const __nv_bfloat16* __restrict__ A, const __nv_bfloat16* __restrict__ B,
                float* __restrict__ C, int Kp, int Nact)
{
    __shared__ __align__(16) __nv_bfloat16 sA[2][128 * SROW];
    __shared__ __align__(16) __nv_bfloat16 sB[2][64 * SROW];

    int tid  = threadIdx.x;
    int wid  = tid >> 5, lane = tid & 31;
    int wm   = (wid >> 1) * 32;
    int wn   = (wid & 1) * 32;
    int bm   = blockIdx.y * 128;
    int bn   = blockIdx.x * 64;

    const __nv_bfloat16* Ab = A + (size_t)bm * Kp;
    const __nv_bfloat16* Bb = B + (size_t)bn * Kp;

    uint32_t uA = smem_to_u32(sA);
    uint32_t uB = smem_to_u32(sB);

    int a_row = wm + (lane & 15);
    int a_ke  = (lane >> 4) * 8;
    int b_row = wn + (lane & 7) + ((lane >> 4) << 3);
    int b_ke  = ((lane >> 3) & 1) * 8;

    float c[2][4][4];
#pragma unroll
    for (int mi = 0; mi < 2; mi++)
#pragma unroll
        for (int ni = 0; ni < 4; ni++)
#pragma unroll
            for (int r = 0; r < 4; r++) c[mi][ni][r] = 0.f;

    const int T = Kp >> 5;

    int arA0 = (tid      ) >> 2, acA0 = (tid      ) & 3;
    int arA1 = (tid + 256) >> 2, acA1 = (tid + 256) & 3;
    int arB  = tid >> 2,         acB  = tid & 3;

    {
        uint4 va0 = *(const uint4*)(Ab + (size_t)arA0 * Kp + acA0 * 8);
        uint4 va1 = *(const uint4*)(Ab + (size_t)arA1 * Kp + acA1 * 8);
        uint4 vb  = *(const uint4*)(Bb + (size_t)arB  * Kp + acB  * 8);
        *(uint4*)(&sA[0][arA0 * SROW + acA0 * 8]) = va0;
        *(uint4*)(&sA[0][arA1 * SROW + acA1 * 8]) = va1;
        *(uint4*)(&sB[0][arB  * SROW + acB  * 8]) = vb;
    }
    __syncthreads();

    for (int t = 0; t < T; t++) {
        int s = t & 1;
        uint4 va0, va1, vb;
        if (t + 1 < T) {
            int k0 = (t + 1) << 5;
            va0 = *(const uint4*)(Ab + (size_t)arA0 * Kp + k0 + acA0 * 8);
            va1 = *(const uint4*)(Ab + (size_t)arA1 * Kp + k0 + acA1 * 8);
            vb  = *(const uint4*)(Bb + (size_t)arB  * Kp + k0 + acB  * 8);
        }

        uint32_t baseA = uA + (uint32_t)(s * 128 * SROW * 2);
        uint32_t baseB = uB + (uint32_t)(s * 64 * SROW * 2);
#pragma unroll
        for (int kk = 0; kk < 2; kk++) {
            uint32_t a0[4], a1[4], b0[4], b1[4];
            LDSM_X4(a0[0], a0[1], a0[2], a0[3],
                    baseA + (uint32_t)(((a_row      ) * SROW + kk * 16 + a_ke) * 2));
            LDSM_X4(a1[0], a1[1], a1[2], a1[3],
                    baseA + (uint32_t)(((a_row + 16 ) * SROW + kk * 16 + a_ke) * 2));
            LDSM_X4(b0[0], b0[1], b0[2], b0[3],
                    baseB + (uint32_t)(((b_row      ) * SROW + kk * 16 + b_ke) * 2));
            LDSM_X4(b1[0], b1[1], b1[2], b1[3],
                    baseB + (uint32_t)(((b_row + 16 ) * SROW + kk * 16 + b_ke) * 2));
#pragma unroll
            for (int mi = 0; mi < 2; mi++) {
                uint32_t* aa = mi ? a1 : a0;
                MMA_BF16(c[mi][0][0], c[mi][0][1], c[mi][0][2], c[mi][0][3],
                         aa[0], aa[1], aa[2], aa[3], b0[0], b0[1]);
                MMA_BF16(c[mi][1][0], c[mi][1][1], c[mi][1][2], c[mi][1][3],
                         aa[0], aa[1], aa[2], aa[3], b0[2], b0[3]);
                MMA_BF16(c[mi][2][0], c[mi][2][1], c[mi][2][2], c[mi][2][3],
                         aa[0], aa[1], aa[2], aa[3], b1[0], b1[1]);
                MMA_BF16(c[mi][3][0], c[mi][3][1], c[mi][3][2], c[mi][3][3],
                         aa[0], aa[1], aa[2], aa[3], b1[2], b1[3]);
            }
        }

        if (t + 1 < T) {
            int ns = (t + 1) & 1;
            *(uint4*)(&sA[ns][arA0 * SROW + acA0 * 8]) = va0;
            *(uint4*)(&sA[ns][arA1 * SROW + acA1 * 8]) = va1;
            *(uint4*)(&sB[ns][arB  * SROW + acB  * 8]) = vb;
        }
        __syncthreads();
    }

#pragma unroll
    for (int mi = 0; mi < 2; mi++) {
        int r0 = bm + wm + mi * 16 + (lane >> 2);
#pragma unroll
        for (int ni = 0; ni < 4; ni++) {
            int col = bn + wn + ni * 8 + (lane & 3) * 2;
            if (col < Nact) {
                *(float2*)(C + (size_t)r0 * Nact + col) =
                    make_float2(c[mi][ni][0], c[mi][ni][1]);
                *(float2*)(C + (size_t)(r0 + 8) * Nact + col) =
                    make_float2(c[mi][ni][2], c[mi][ni][3]);
            }
        }
    }
}

// ==================== linear attention ========================================
__global__ void clear_kv_kernel()
{
    int i = blockIdx.x * blockDim.x + threadIdx.x;
    if (i < BB * HH * EE * EE) g_kv[i] = 0.f;
    if (i < BB * HH * EE)      g_ksum[i] = 0.f;
}

#define KV_SEGS 16
__global__ void lin_kv_kernel()
{
    int bh  = blockIdx.x;
    int seg = blockIdx.y;
    int b = bh >> 4, h = bh & 15;
    int n0base = seg * (SS / KV_SEGS);

    __shared__ float sk[64][FF];
    __shared__ float sv[64][EE];

    int tid = threadIdx.x;
    const int NITEMS = EE * EE + EE;

    float acc[5];
    int   di[5], ei[5];
    int cnt = 0;
    for (int it = tid; it < NITEMS; it += 256) {
        acc[cnt] = 0.f;
        if (it < EE * EE) { di[cnt] = it / EE; ei[cnt] = it % EE; }
        else              { di[cnt] = it - EE * EE; ei[cnt] = -1; }
        cnt++;
    }

    for (int c0 = 0; c0 < SS / KV_SEGS; c0 += 64) {
        int n0 = n0base + c0;
        {
            int r = tid >> 2, f = (tid & 3) * 4;
            const float4 k4 = *(const float4*)(g_qkv_lin + ((size_t)(b * SS + n0 + r)) * NLIN + 256 + h * FF + f);
            sk[r][f + 0] = k4.x; sk[r][f + 1] = k4.y; sk[r][f + 2] = k4.z; sk[r][f + 3] = k4.w;
        }
        for (int i = tid; i < 64 * EE; i += 256) {
            int r = i / EE, e = i % EE;
            sv[r][e] = g_qkv_lin[((size_t)(b * SS + n0 + r)) * NLIN + 512 + h * EE + e];
        }
        __syncthreads();

        for (int u = 0; u < cnt; u++) {
            int d = di[u], e = ei[u];
            float a = acc[u];
            if (e >= 0) {
                if (d == 0) {
                    for (int nn = 0; nn < 64; nn++) a += sv[nn][e];
                } else if (d <= FF) {
                    int dd = d - 1;
                    for (int nn = 0; nn < 64; nn++) a += sk[nn][dd] * sv[nn][e];
                } else {
                    int dd = d - 1 - FF;
                    for (int nn = 0; nn < 64; nn++) { float kk = sk[nn][dd]; a += 0.5f * kk * kk * sv[nn][e]; }
                }
            } else {
                if (d == 0) {
                    a += 64.f;
                } else if (d <= FF) {
                    int dd = d - 1;
                    for (int nn = 0; nn < 64; nn++) a += sk[nn][dd];
                } else {
                    int dd = d - 1 - FF;
                    for (int nn = 0; nn < 64; nn++) { float kk = sk[nn][dd]; a += 0.5f * kk * kk; }
                }
            }
            acc[u] = a;
        }
        __syncthreads();
    }

    for (int u = 0; u < cnt; u++) {
        if (ei[u] >= 0) atomicAdd(&g_kv[((size_t)bh) * EE * EE + di[u] * EE + ei[u]], acc[u]);
        else            atomicAdd(&g_ksum[bh * EE + di[u]], acc[u]);
    }
}

// writes its result directly into g_ob concat columns [0, 528)
__global__ void lin_out_kernel(const int* __restrict__ mask)
{
    int s = blockIdx.x, b = blockIdx.y;
    __shared__ float sq[HH * FF];
    int tid = threadIdx.x;
    if (tid < HH * FF) sq[tid] = g_qkv_lin[((size_t)(b * SS + s)) * NLIN + tid];
    __syncthreads();
    if (tid >= DD) return;

    int h = tid / EE, e = tid % EE;
    const float* kv = g_kv + ((size_t)(b * HH + h)) * EE * EE;
    const float* q  = sq + h * FF;

    float qkv  = kv[e];
    float qsum = 1.f;
#pragma unroll
    for (int j = 0; j < FF; j++) {
        float qa = q[j];
        float q2 = 0.5f * qa * qa;
        qkv  += qa * kv[(1 + j) * EE + e] + q2 * kv[(1 + FF + j) * EE + e];
        qsum += qa + q2;
    }
    float z = qsum * g_ksum[(b * HH + h) * EE + e];
    float out = qkv / (z + 1e-9f);
    if (mask[b * SS + s] == 0) out = 0.f;
    store_ob3((size_t)(b * SS + s) * KP2, tid, out);
}

// ==================== tf32 MMA flash window attention =========================
// Round-12 contiguous K/V layouts + double buffering + ballot mask bitmask with
// full-tile fast path + exp2-domain softmax (scale folded with log2 e).
// smem floats: sS 128*68 (8704) | sK 2*64*44 | sV 2*64*56 | 4 mask words @21504
#define WM_SMEM (21632*4)

__global__ void __launch_bounds__(256)
win_mma_kernel(const int* __restrict__ mask)
{
    extern __shared__ float smf[];
    float* sS = smf;                    // 128*68
    unsigned* maskw = (unsigned*)(smf + 21504);

    int qt = (int)gridDim.x - 1 - (int)blockIdx.x;
    int bh = blockIdx.y; int b = bh >> 4, h = bh & 15;
    int tid = threadIdx.x, wid = tid >> 5, lane = tid & 31;
    int g = lane >> 2, t = lane & 3;
    int rw = wid * 16;
    int q0 = qt * 128;
    int kend = min(SS, q0 + 127 + WIN);
    const float scale = 0.17407765595569785f * 1.44269504088896340736f; // 1/sqrt(33)*log2(e)

    int pr[10], pd[10];
#pragma unroll
    for (int j = 0; j < 10; j++) { int i = tid + j * 256; pr[j] = i / 40; pd[j] = i - pr[j] * 40; }

    // stage Q (pre-scaled into log2 domain, tf32) into sS; extract A fragments
    for (int i = tid; i < 128 * 40; i += 256) {
        int r = i / 40, d = i - r * 40;
        float v = (d < EE) ? g_qkv_win[((size_t)(b * SS + q0 + r)) * NWIN + h * EE + d] * scale : 0.f;
        sS[r * 68 + d] = to_tf32(v);
    }
    __syncthreads();
    uint32_t aq[5][4];
#pragma unroll
    for (int kc = 0; kc < 5; kc++) {
        aq[kc][0] = __float_as_uint(sS[(rw + g    ) * 68 + kc * 8 + t    ]);
        aq[kc][1] = __float_as_uint(sS[(rw + g + 8) * 68 + kc * 8 + t    ]);
        aq[kc][2] = __float_as_uint(sS[(rw + g    ) * 68 + kc * 8 + t + 4]);
        aq[kc][3] = __float_as_uint(sS[(rw + g + 8) * 68 + kc * 8 + t + 4]);
    }
    __syncthreads();

    float co[5][4];
#pragma unroll
    for (int n = 0; n < 5; n++)
#pragma unroll
        for (int r = 0; r < 4; r++) co[n][r] = 0.f;
    float mrun0 = -1e30f, mrun1 = -1e30f, lsum0 = 0.f, lsum1 = 0.f;

    const int T = (kend + 63) >> 6;
    float kr_[10], vr_[10]; int mk_;

    // prologue: load tile 0 into regs, stage into buffer 0
    {
        int nv = min(64, kend);
#pragma unroll
        for (int j = 0; j < 10; j++) {
            bool ok = (pr[j] < nv) && (pd[j] < EE);
            size_t rowb = ((size_t)(b * SS + pr[j])) * NWIN;
            kr_[j] = ok ? g_qkv_win[rowb + 576 + h * EE + pd[j]] : 0.f;
            vr_[j] = ok ? g_qkv_win[rowb + 1152 + h * EE + pd[j]] : 0.f;
        }
        mk_ = (tid < 64) ? ((tid < nv) ? mask[b * SS + tid] : 0) : 0;
#pragma unroll
        for (int j = 0; j < 10; j++) {
            smf[8704 + pr[j] * 44 + pd[j]]  = to_tf32(kr_[j]);
            smf[14336 + pr[j] * 56 + pd[j]] = to_tf32(vr_[j]);
        }
        if (wid < 2) {
            unsigned bal = __ballot_sync(0xffffffffu, mk_ != 0);
            if (lane == 0) maskw[wid] = bal;
        }
    }
    __syncthreads();

    for (int tt = 0; tt < T; tt++) {
        int buf = tt & 1;
        int kt = tt << 6;
        float* sK = smf + 8704  + buf * 2816;
        float* sV = smf + 14336 + buf * 3584;
        uint64_t mbits = ((uint64_t)maskw[buf * 2 + 1] << 32) | maskw[buf * 2];

        // prefetch tile tt+1 into registers
        if (tt + 1 < T) {
            int ktn = (tt + 1) << 6;
            int nv = min(64, kend - ktn);
#pragma unroll
            for (int j = 0; j < 10; j++) {
                bool ok = (pr[j] < nv) && (pd[j] < EE);
                size_t rowb = ((size_t)(b * SS + ktn + pr[j])) * NWIN;
                kr_[j] = ok ? g_qkv_win[rowb + 576 + h * EE + pd[j]] : 0.f;
                vr_[j] = ok ? g_qkv_win[rowb + 1152 + h * EE + pd[j]] : 0.f;
            }
            mk_ = (tid < 64) ? ((tid < nv) ? mask[b * SS + ktn + tid] : 0) : 0;
        }

        // --- QK^T: S[16 x 64] per warp ---
        float cs[8][4];
#pragma unroll
        for (int n = 0; n < 8; n++)
#pragma unroll
            for (int r = 0; r < 4; r++) cs[n][r] = 0.f;
#pragma unroll
        for (int kc = 0; kc < 5; kc++)
#pragma unroll
            for (int n = 0; n < 8; n++) {
                uint32_t b0 = __float_as_uint(sK[(n * 8 + g) * 44 + kc * 8 + t    ]);
                uint32_t b1 = __float_as_uint(sK[(n * 8 + g) * 44 + kc * 8 + t + 4]);
                MMA_TF32(cs[n], aq[kc][0], aq[kc][1], aq[kc][2], aq[kc][3], b0, b1);
            }

        // --- mask IN PLACE (bitmask; fast path for full tiles) ---
        if (!(mbits == ~0ull && kt <= q0)) {
            int r0g = q0 + rw + g, r1g = r0g + 8;
#pragma unroll
            for (int n = 0; n < 8; n++) {
                int c0 = n * 8 + 2 * t;
                int cg0 = kt + c0, cg1 = cg0 + 1;
                bool m0 = (mbits >> c0) & 1, m1 = (mbits >> (c0 + 1)) & 1;
                if (!(m0 && cg0 <= r0g + WIN - 1)) cs[n][0] = -1e30f;
                if (!(m1 && cg1 <= r0g + WIN - 1)) cs[n][1] = -1e30f;
                if (!(m0 && cg0 <= r1g + WIN - 1)) cs[n][2] = -1e30f;
                if (!(m1 && cg1 <= r1g + WIN - 1)) cs[n][3] = -1e30f;
            }
        }

        // --- warp-local online softmax (log2 domain), exp IN PLACE ---
        float mx0 = -1e30f, mx1 = -1e30f;
#pragma unroll
        for (int n = 0; n < 8; n++) {
            mx0 = fmaxf(mx0, fmaxf(cs[n][0], cs[n][1]));
            mx1 = fmaxf(mx1, fmaxf(cs[n][2], cs[n][3]));
        }
        mx0 = fmaxf(mx0, __shfl_xor_sync(0xffffffffu, mx0, 1));
        mx0 = fmaxf(mx0, __shfl_xor_sync(0xffffffffu, mx0, 2));
        mx1 = fmaxf(mx1, __shfl_xor_sync(0xffffffffu, mx1, 1));
        mx1 = fmaxf(mx1, __shfl_xor_sync(0xffffffffu, mx1, 2));
        float mn0 = fmaxf(mrun0, mx0), mn1 = fmaxf(mrun1, mx1);
        float fac0 = ex2f(mrun0 - mn0), fac1 = ex2f(mrun1 - mn1);
        float ps0 = 0.f, ps1 = 0.f;
#pragma unroll
        for (int n = 0; n < 8; n++) {
            cs[n][0] = ex2f(cs[n][0] - mn0); ps0 += cs[n][0];
            cs[n][1] = ex2f(cs[n][1] - mn0); ps0 += cs[n][1];
            cs[n][2] = ex2f(cs[n][2] - mn1); ps1 += cs[n][2];
            cs[n][3] = ex2f(cs[n][3] - mn1); ps1 += cs[n][3];
        }
        ps0 += __shfl_xor_sync(0xffffffffu, ps0, 1);
        ps0 += __shfl_xor_sync(0xffffffffu, ps0, 2);
        ps1 += __shfl_xor_sync(0xffffffffu, ps1, 1);
        ps1 += __shfl_xor_sync(0xffffffffu, ps1, 2);
        lsum0 = lsum0 * fac0 + ps0; mrun0 = mn0;
        lsum1 = lsum1 * fac1 + ps1; mrun1 = mn1;

        // --- stage P (tf32) into own rows of sS (warp-local) ---
#pragma unroll
        for (int n = 0; n < 8; n++) {
            int c0 = n * 8 + 2 * t;
            *(float2*)&sS[(rw + g    ) * 68 + c0] = make_float2(to_tf32(cs[n][0]), to_tf32(cs[n][1]));
            *(float2*)&sS[(rw + g + 8) * 68 + c0] = make_float2(to_tf32(cs[n][2]), to_tf32(cs[n][3]));
        }
        __syncwarp();

        // --- rescale + P @ V ---
#pragma unroll
        for (int n = 0; n < 5; n++) {
            co[n][0] *= fac0; co[n][1] *= fac0; co[n][2] *= fac1; co[n][3] *= fac1;
        }
#pragma unroll
        for (int kc = 0; kc < 8; kc++) {
            uint32_t a0 = __float_as_uint(sS[(rw + g    ) * 68 + kc * 8 + t    ]);
            uint32_t a1 = __float_as_uint(sS[(rw + g + 8) * 68 + kc * 8 + t    ]);
            uint32_t a2 = __float_as_uint(sS[(rw + g    ) * 68 + kc * 8 + t + 4]);
            uint32_t a3 = __float_as_uint(sS[(rw + g + 8) * 68 + kc * 8 + t + 4]);
#pragma unroll
            for (int n = 0; n < 5; n++) {
                uint32_t b0 = __float_as_uint(sV[(kc * 8 + t    ) * 56 + n * 8 + g]);
                uint32_t b1 = __float_as_uint(sV[(kc * 8 + t + 4) * 56 + n * 8 + g]);
                MMA_TF32(co[n], a0, a1, a2, a3, b0, b1);
            }
        }

        // --- store prefetched tile into the other buffer ---
        if (tt + 1 < T) {
            int nb = 1 - buf;
            float* nK = smf + 8704  + nb * 2816;
            float* nV = smf + 14336 + nb * 3584;
#pragma unroll
            for (int j = 0; j < 10; j++) {
                nK[pr[j] * 44 + pd[j]] = to_tf32(kr_[j]);
                nV[pr[j] * 56 + pd[j]] = to_tf32(vr_[j]);
            }
            if (wid < 2) {
                unsigned bal = __ballot_sync(0xffffffffu, mk_ != 0);
                if (lane == 0) maskw[nb * 2 + wid] = bal;
            }
        }
        __syncthreads();
    }

    float inv0 = 1.f / lsum0, inv1 = 1.f / lsum1;
    int r0 = q0 + rw + g, r1 = r0 + 8;
    size_t base0 = (size_t)(b * SS + r0) * KP2;
    size_t base1 = (size_t)(b * SS + r1) * KP2;
    int colbase = DD + h * EE;
#pragma unroll
    for (int n = 0; n < 5; n++) {
        int c0 = n * 8 + 2 * t;
        if (c0 < EE) {
            store_ob3(base0, colbase + c0, co[n][0] * inv0);
            store_ob3(base1, colbase + c0, co[n][2] * inv1);
        }
        if (c0 + 1 < EE) {
            store_ob3(base0, colbase + c0 + 1, co[n][1] * inv0);
            store_ob3(base1, colbase + c0 + 1, co[n][3] * inv1);
        }
    }
}

// ==================== launcher ================================================
extern "C" void kernel_launch(void* const* d_in, const int* in_sizes, int n_in,
                              void* d_out, int out_size)
{
    const float* x      = (const float*)d_in[0];
    const int*   mask   = (const int*)  d_in[1];
    const float* Wq_lin = (const float*)d_in[2];
    const float* Wk_lin = (const float*)d_in[3];
    const float* Wv_lin = (const float*)d_in[4];
    const float* Wo_lin = (const float*)d_in[5];
    const float* Wq_win = (const float*)d_in[6];
    const float* Wk_win = (const float*)d_in[7];
    const float* Wv_win = (const float*)d_in[8];
    const float* Wo_win = (const float*)d_in[9];
    float* out = (float*)d_out;

    float *p_qkv_lin, *p_qkv_win, *p_wlinb;
    __nv_bfloat16 *p_xb, *p_ob, *p_wwinb, *p_wob;
    cudaGetSymbolAddress((void**)&p_qkv_lin, g_qkv_lin);
    cudaGetSymbolAddress((void**)&p_qkv_win, g_qkv_win);
    cudaGetSymbolAddress((void**)&p_wlinb,   g_wlinb);
    cudaGetSymbolAddress((void**)&p_xb,   g_xb);
    cudaGetSymbolAddress((void**)&p_ob,   g_ob);
    cudaGetSymbolAddress((void**)&p_wwinb, g_wwinb);
    cudaGetSymbolAddress((void**)&p_wob,  g_wob);

    static cudaStream_t s_win = 0;
    static cudaEvent_t  evFork = 0, evJoin = 0;
    if (s_win == 0) {
        cudaStreamCreateWithFlags(&s_win, cudaStreamNonBlocking);
        cudaEventCreateWithFlags(&evFork, cudaEventDisableTiming);
        cudaEventCreateWithFlags(&evJoin, cudaEventDisableTiming);
        cudaFuncSetAttribute(win_mma_kernel, cudaFuncAttributeMaxDynamicSharedMemorySize, WM_SMEM);
    }

    // -------- fork win chain off the capture stream --------
    cudaEventRecord(evFork, 0);
    cudaStreamWaitEvent(s_win, evFork, 0);

    // win chain (s_win): splits -> merged HMMA projection -> tf32 flash attn
    split_x_kernel<<<(MTOT*KP1 + 255)/256, 256, 0, s_win>>>(x);
    split_wwin_kernel<<<dim3(KP1/32, NWIN/32), dim3(32, 8), 0, s_win>>>(Wq_win, Wk_win, Wv_win);
    gemm_mma_kernel<<<dim3(NWIN/64, MTOT/128), 256, 0, s_win>>>(p_xb, p_wwinb, p_qkv_win, KP1, NWIN);
    win_mma_kernel<<<dim3(SS/128, BB*HH), 256, WM_SMEM, s_win>>>(mask);

    // lin chain (capture stream): wo split + merged fp32 projection -> linear attn
    split_wo_kernel<<<dim3(KP2/32, NP_D/32), dim3(32, 8)>>>(Wo_lin, Wo_win);
    concat_wlin_kernel<<<(DD*NLIN + 255)/256, 256>>>(Wq_lin, Wk_lin, Wv_lin);
    gemm_lin_kernel<<<dim3((NLIN + LN - 1)/LN, MTOT/LM), 256>>>(x, p_wlinb, p_qkv_lin, MTOT, NLIN, DD);
    clear_kv_kernel<<<(BB*HH*EE*EE + 255)/256, 256>>>();
    lin_kv_kernel<<<dim3(BB*HH, KV_SEGS), 256>>>();
    lin_out_kernel<<<dim3(SS, BB), 544>>>(mask);

    // -------- join, then fused output projection --------
    cudaEventRecord(evJoin, s_win);
    cudaStreamWaitEvent(0, evJoin, 0);
    gemm_mma_kernel<<<dim3(NP_D/64, MTOT/128), 256>>>(p_ob, p_wob, out, KP2, DD);
}

// round 16
// speedup vs baseline: 1.1090x; 1.0497x over previous
#include <cuda_runtime.h>
#include <cuda_bf16.h>
#include <math.h>
#include <stdint.h>

#define BB 2
#define SS 2048
#define DD 528
#define HH 16
#define FF 16
#define EE 33            // HEAD_DIM = 2*FF+1
#define MTOT (BB*SS)     // 4096
#define WIN 64

#define KP1 1600         // padded 3*528
#define KP2 3200         // padded 3*1056
#define KC  1056         // concat K for output GEMM
#define NP_D  576        // 528 padded to 64 multiple
#define NWIN 1728        // 3*576 concat win projection width
#define NLIN 1040        // 256+256+528 concat lin projection width

// ---------------- scratch (device globals; no allocations allowed) -------------
static __device__ __align__(128) float g_qkv_lin[MTOT*NLIN];   // [q(256)|k(256)|v(528)]
static __device__ __align__(128) float g_qkv_win[MTOT*NWIN];   // [q(576)|k(576)|v(576)]
static __device__ __align__(128) float g_wlinb[DD*NLIN];
static __device__ __align__(128) float g_kv[BB*HH*EE*EE];
static __device__ __align__(128) float g_ksum[BB*HH*EE];

// bf16 split operands
static __device__ __align__(128) __nv_bfloat16 g_xb [MTOT*KP1];
static __device__ __align__(128) __nv_bfloat16 g_ob [MTOT*KP2];   // padding cols stay 0
static __device__ __align__(128) __nv_bfloat16 g_wwinb[NWIN*KP1]; // [Wq|Wk|Wv]_win split
static __device__ __align__(128) __nv_bfloat16 g_wob [NP_D*KP2];

// ==================== helpers =================================================
__device__ __forceinline__ uint32_t smem_to_u32(const void* p) {
    uint32_t a;
    asm("{ .reg .u64 t; cvta.to.shared.u64 t, %1; cvt.u32.u64 %0, t; }" : "=r"(a) : "l"(p));
    return a;
}
#define LDSM_X4(r0, r1, r2, r3, addr) \
    asm volatile("ldmatrix.sync.aligned.m8n8.x4.shared.b16 {%0,%1,%2,%3}, [%4];" \
        : "=r"(r0), "=r"(r1), "=r"(r2), "=r"(r3) : "r"(addr))
#define MMA_BF16(c0, c1, c2, c3, a0, a1, a2, a3, b0, b1) \
    asm volatile("mma.sync.aligned.m16n8k16.row.col.f32.bf16.bf16.f32 " \
        "{%0,%1,%2,%3}, {%4,%5,%6,%7}, {%8,%9}, {%0,%1,%2,%3};" \
        : "+f"(c0), "+f"(c1), "+f"(c2), "+f"(c3) \
        : "r"(a0), "r"(a1), "r"(a2), "r"(a3), "r"(b0), "r"(b1))
#define MMA_TF32(c, a0, a1, a2, a3, b0, b1) \
    asm volatile("mma.sync.aligned.m16n8k8.row.col.f32.tf32.tf32.f32 " \
        "{%0,%1,%2,%3}, {%4,%5,%6,%7}, {%8,%9}, {%0,%1,%2,%3};" \
        : "+f"((c)[0]), "+f"((c)[1]), "+f"((c)[2]), "+f"((c)[3]) \
        : "r"(a0), "r"(a1), "r"(a2), "r"(a3), "r"(b0), "r"(b1))
__device__ __forceinline__ float to_tf32(float v) {
    uint32_t u; asm("cvt.rna.tf32.f32 %0, %1;" : "=r"(u) : "f"(v));
    return __uint_as_float(u);
}
__device__ __forceinline__ float ex2f(float x) {
    float r; asm("ex2.approx.ftz.f32 %0, %1;" : "=f"(r) : "f"(x)); return r;
}
__device__ __forceinline__ void store_ob3(size_t base, int col, float v) {
    __nv_bfloat16 hi = __float2bfloat16(v);
    __nv_bfloat16 lo = __float2bfloat16(v - __bfloat162float(hi));
    g_ob[base + col]          = hi;
    g_ob[base + KC + col]     = lo;
    g_ob[base + 2 * KC + col] = hi;
}

// ==================== conversion / concat kernels =============================
__global__ void split_x_kernel(const float* __restrict__ x)
{
    int idx = blockIdx.x * blockDim.x + threadIdx.x;
    if (idx >= MTOT * KP1) return;
    int k = idx % KP1, m = idx / KP1;
    __nv_bfloat16 o;
    if (k < DD)            o = __float2bfloat16(x[m*DD + k]);
    else if (k < 2*DD) { float f = x[m*DD + k - DD]; __nv_bfloat16 h = __float2bfloat16(f);
                         o = __float2bfloat16(f - __bfloat162float(h)); }
    else if (k < 3*DD)     o = __float2bfloat16(x[m*DD + k - 2*DD]);
    else                   o = __float2bfloat16(0.f);
    g_xb[idx] = o;
}

// coalesced win weight split via 32x32 smem transpose. grid (KP1/32, NWIN/32), block (32,8)
__global__ void split_wwin_kernel(const float* __restrict__ Wq, const float* __restrict__ Wk,
                                  const float* __restrict__ Wv)
{
    __shared__ float tile[32][33];
    int kt0 = blockIdx.x * 32, nt0 = blockIdx.y * 32;
    for (int kk = threadIdx.y; kk < 32; kk += 8) {
        int k = kt0 + kk;
        int ng = nt0 + threadIdx.x;
        int sel = ng / NP_D, nn = ng - sel * NP_D;
        float f = 0.f;
        if (k < 3*DD && nn < DD) {
            int k0 = (k < DD) ? k : ((k < 2*DD) ? k - DD : k - 2*DD);
            const float* W = (sel == 0) ? Wq : ((sel == 1) ? Wk : Wv);
            f = W[(size_t)k0 * DD + nn];
        }
        tile[kk][threadIdx.x] = f;
    }
    __syncthreads();
    for (int nn2 = threadIdx.y; nn2 < 32; nn2 += 8) {
        int n = nt0 + nn2;
        int k = kt0 + threadIdx.x;
        float f = tile[threadIdx.x][nn2];
        __nv_bfloat16 h = __float2bfloat16(f);
        __nv_bfloat16 o = (k < 2*DD) ? h : __float2bfloat16(f - __bfloat162float(h));
        g_wwinb[(size_t)n * KP1 + k] = o;
    }
}

// coalesced output-weight split. grid (KP2/32, NP_D/32), block (32,8)
__global__ void split_wo_kernel(const float* __restrict__ Wol, const float* __restrict__ Wow)
{
    __shared__ float tile[32][33];
    int kt0 = blockIdx.x * 32, nt0 = blockIdx.y * 32;
    for (int kk = threadIdx.y; kk < 32; kk += 8) {
        int k = kt0 + kk;
        int n = nt0 + threadIdx.x;
        float f = 0.f;
        if (k < 3*KC && n < DD) {
            int k0 = k % KC;
            f = (k0 < DD) ? Wol[(size_t)k0 * DD + n] : Wow[(size_t)(k0 - DD) * DD + n];
        }
        tile[kk][threadIdx.x] = f;
    }
    __syncthreads();
    for (int nn2 = threadIdx.y; nn2 < 32; nn2 += 8) {
        int n = nt0 + nn2;
        int k = kt0 + threadIdx.x;
        float f = tile[threadIdx.x][nn2];
        __nv_bfloat16 h = __float2bfloat16(f);
        __nv_bfloat16 o = (k < 2*KC) ? h : __float2bfloat16(f - __bfloat162float(h));
        g_wob[(size_t)n * KP2 + k] = o;
    }
}

__global__ void concat_wlin_kernel(const float* __restrict__ Wq, const float* __restrict__ Wk,
                                   const float* __restrict__ Wv)
{
    int idx = blockIdx.x * blockDim.x + threadIdx.x;
    if (idx >= DD * NLIN) return;
    int k = idx / NLIN, n = idx % NLIN;
    float v;
    if (n < 256)      v = Wq[(size_t)k * 256 + n];
    else if (n < 512) v = Wk[(size_t)k * 256 + n - 256];
    else              v = Wv[(size_t)k * DD  + n - 512];
    g_wlinb[idx] = v;
}

// ==================== fp32 SIMT GEMM (lin path), 128x128 tile, 8x8 micro ======
#define LM 128
#define LN 128
#define LK 16

__global__ void __launch_bounds__(256)
gemm_lin_kernel(const float* __restrict__ A, const float* __restrict__ B,
                float* __restrict__ C, int M, int N, int K)
{
    __shared__ float As[LK][LM];
    __shared__ float Bs[LK][LN + 4];

    int tid = threadIdx.x;
    int tx = tid & 15, ty = tid >> 4;
    int bm = blockIdx.y * LM, bn = blockIdx.x * LN;

    float c[8][8];
#pragma unroll
    for (int i = 0; i < 8; i++)
#pragma unroll
        for (int j = 0; j < 8; j++) c[i][j] = 0.f;

    int ra = tid & 127, ka = (tid >> 7) * 8;
    int kb = tid >> 4, cb = (tid & 15) * 4;

    const float* Ag = A + (size_t)(bm + ra) * K + ka;
    const float* Bg = B + (size_t)kb * N + bn;
    bool ok0 = (bn + cb) < N;
    bool ok1 = (bn + 64 + cb) < N;

    const int T = K / LK;
    float4 va0, va1, vb0, vb1;
    va0 = *(const float4*)(Ag);
    va1 = *(const float4*)(Ag + 4);
    vb0 = ok0 ? *(const float4*)(Bg + cb)      : make_float4(0.f, 0.f, 0.f, 0.f);
    vb1 = ok1 ? *(const float4*)(Bg + 64 + cb) : make_float4(0.f, 0.f, 0.f, 0.f);

    for (int t = 0; t < T; t++) {
        As[ka + 0][ra] = va0.x; As[ka + 1][ra] = va0.y;
        As[ka + 2][ra] = va0.z; As[ka + 3][ra] = va0.w;
        As[ka + 4][ra] = va1.x; As[ka + 5][ra] = va1.y;
        As[ka + 6][ra] = va1.z; As[ka + 7][ra] = va1.w;
        *(float4*)&Bs[kb][cb]      = vb0;
        *(float4*)&Bs[kb][64 + cb] = vb1;
        __syncthreads();

        if (t + 1 < T) {
            int k0 = (t + 1) * LK;
            va0 = *(const float4*)(Ag + k0);
            va1 = *(const float4*)(Ag + k0 + 4);
            const float* Bt = Bg + (size_t)k0 * N;
            vb0 = ok0 ? *(const float4*)(Bt + cb)      : make_float4(0.f, 0.f, 0.f, 0.f);
            vb1 = ok1 ? *(const float4*)(Bt + 64 + cb) : make_float4(0.f, 0.f, 0.f, 0.f);
        }

#pragma unroll
        for (int k = 0; k < LK; k++) {
            float a[8], b[8];
            *(float4*)&a[0] = *(const float4*)&As[k][ty * 4];
            *(float4*)&a[4] = *(const float4*)&As[k][64 + ty * 4];
            *(float4*)&b[0] = *(const float4*)&Bs[k][tx * 4];
            *(float4*)&b[4] = *(const float4*)&Bs[k][64 + tx * 4];
#pragma unroll
            for (int i = 0; i < 8; i++)
#pragma unroll
                for (int j = 0; j < 8; j++) c[i][j] += a[i] * b[j];
        }
        __syncthreads();
    }

#pragma unroll
    for (int ih = 0; ih < 2; ih++)
#pragma unroll
    for (int i = 0; i < 4; i++) {
        int row = bm + ih * 64 + ty * 4 + i;
        float* Crow = C + (size_t)row * N;
#pragma unroll
        for (int jh = 0; jh < 2; jh++) {
            int col = bn + jh * 64 + tx * 4;
            if (col < N) {
                *(float4*)(Crow + col) = make_float4(c[ih*4+i][jh*4+0], c[ih*4+i][jh*4+1],
                                                     c[ih*4+i][jh*4+2], c[ih*4+i][jh*4+3]);
            }
        }
    }
}

// ==================== HMMA (mma.sync) bf16 GEMM ===============================
#define SROW 40

__global__ void __launch_bounds__(256)
gemm_mma_kernel(const __nv_bfloat16* __restrict__ A, const __nv_bfloat16* __restrict__ B,
                float* __restrict__ C, int Kp, int Nact)
{
    __shared__ __align__(16) __nv_bfloat16 sA[2][128 * SROW];
    __shared__ __align__(16) __nv_bfloat16 sB[2][64 * SROW];

    int tid  = threadIdx.x;
    int wid  = tid >> 5, lane = tid & 31;
    int wm   = (wid >> 1) * 32;
    int wn   = (wid & 1) * 32;
    int bm   = blockIdx.y * 128;
    int bn   = blockIdx.x * 64;

    const __nv_bfloat16* Ab = A + (size_t)bm * Kp;
    const __nv_bfloat16* Bb = B + (size_t)bn * Kp;

    uint32_t uA = smem_to_u32(sA);
    uint32_t uB = smem_to_u32(sB);

    int a_row = wm + (lane & 15);
    int a_ke  = (lane >> 4) * 8;
    int b_row = wn + (lane & 7) + ((lane >> 4) << 3);
    int b_ke  = ((lane >> 3) & 1) * 8;

    float c[2][4][4];
#pragma unroll
    for (int mi = 0; mi < 2; mi++)
#pragma unroll
        for (int ni = 0; ni < 4; ni++)
#pragma unroll
            for (int r = 0; r < 4; r++) c[mi][ni][r] = 0.f;

    const int T = Kp >> 5;

    int arA0 = (tid      ) >> 2, acA0 = (tid      ) & 3;
    int arA1 = (tid + 256) >> 2, acA1 = (tid + 256) & 3;
    int arB  = tid >> 2,         acB  = tid & 3;

    {
        uint4 va0 = *(const uint4*)(Ab + (size_t)arA0 * Kp + acA0 * 8);
        uint4 va1 = *(const uint4*)(Ab + (size_t)arA1 * Kp + acA1 * 8);
        uint4 vb  = *(const uint4*)(Bb + (size_t)arB  * Kp + acB  * 8);
        *(uint4*)(&sA[0][arA0 * SROW + acA0 * 8]) = va0;
        *(uint4*)(&sA[0][arA1 * SROW + acA1 * 8]) = va1;
        *(uint4*)(&sB[0][arB  * SROW + acB  * 8]) = vb;
    }
    __syncthreads();

    for (int t = 0; t < T; t++) {
        int s = t & 1;
        uint4 va0, va1, vb;
        if (t + 1 < T) {
            int k0 = (t + 1) << 5;
            va0 = *(const uint4*)(Ab + (size_t)arA0 * Kp + k0 + acA0 * 8);
            va1 = *(const uint4*)(Ab + (size_t)arA1 * Kp + k0 + acA1 * 8);
            vb  = *(const uint4*)(Bb + (size_t)arB  * Kp + k0 + acB  * 8);
        }

        uint32_t baseA = uA + (uint32_t)(s * 128 * SROW * 2);
        uint32_t baseB = uB + (uint32_t)(s * 64 * SROW * 2);
#pragma unroll
        for (int kk = 0; kk < 2; kk++) {
            uint32_t a0[4], a1[4], b0[4], b1[4];
            LDSM_X4(a0[0], a0[1], a0[2], a0[3],
                    baseA + (uint32_t)(((a_row      ) * SROW + kk * 16 + a_ke) * 2));
            LDSM_X4(a1[0], a1[1], a1[2], a1[3],
                    baseA + (uint32_t)(((a_row + 16 ) * SROW + kk * 16 + a_ke) * 2));
            LDSM_X4(b0[0], b0[1], b0[2], b0[3],
                    baseB + (uint32_t)(((b_row      ) * SROW + kk * 16 + b_ke) * 2));
            LDSM_X4(b1[0], b1[1], b1[2], b1[3],
                    baseB + (uint32_t)(((b_row + 16 ) * SROW + kk * 16 + b_ke) * 2));
#pragma unroll
            for (int mi = 0; mi < 2; mi++) {
                uint32_t* aa = mi ? a1 : a0;
                MMA_BF16(c[mi][0][0], c[mi][0][1], c[mi][0][2], c[mi][0][3],
                         aa[0], aa[1], aa[2], aa[3], b0[0], b0[1]);
                MMA_BF16(c[mi][1][0], c[mi][1][1], c[mi][1][2], c[mi][1][3],
                         aa[0], aa[1], aa[2], aa[3], b0[2], b0[3]);
                MMA_BF16(c[mi][2][0], c[mi][2][1], c[mi][2][2], c[mi][2][3],
                         aa[0], aa[1], aa[2], aa[3], b1[0], b1[1]);
                MMA_BF16(c[mi][3][0], c[mi][3][1], c[mi][3][2], c[mi][3][3],
                         aa[0], aa[1], aa[2], aa[3], b1[2], b1[3]);
            }
        }

        if (t + 1 < T) {
            int ns = (t + 1) & 1;
            *(uint4*)(&sA[ns][arA0 * SROW + acA0 * 8]) = va0;
            *(uint4*)(&sA[ns][arA1 * SROW + acA1 * 8]) = va1;
            *(uint4*)(&sB[ns][arB  * SROW + acB  * 8]) = vb;
        }
        __syncthreads();
    }

#pragma unroll
    for (int mi = 0; mi < 2; mi++) {
        int r0 = bm + wm + mi * 16 + (lane >> 2);
#pragma unroll
        for (int ni = 0; ni < 4; ni++) {
            int col = bn + wn + ni * 8 + (lane & 3) * 2;
            if (col < Nact) {
                *(float2*)(C + (size_t)r0 * Nact + col) =
                    make_float2(c[mi][ni][0], c[mi][ni][1]);
                *(float2*)(C + (size_t)(r0 + 8) * Nact + col) =
                    make_float2(c[mi][ni][2], c[mi][ni][3]);
            }
        }
    }
}

// ==================== linear attention ========================================
__global__ void clear_kv_kernel()
{
    int i = blockIdx.x * blockDim.x + threadIdx.x;
    if (i < BB * HH * EE * EE) g_kv[i] = 0.f;
    if (i < BB * HH * EE)      g_ksum[i] = 0.f;
}

#define KV_SEGS 16
__global__ void lin_kv_kernel()
{
    int bh  = blockIdx.x;
    int seg = blockIdx.y;
    int b = bh >> 4, h = bh & 15;
    int n0base = seg * (SS / KV_SEGS);

    __shared__ float sk[64][FF];
    __shared__ float sv[64][EE];

    int tid = threadIdx.x;
    const int NITEMS = EE * EE + EE;

    float acc[5];
    int   di[5], ei[5];
    int cnt = 0;
    for (int it = tid; it < NITEMS; it += 256) {
        acc[cnt] = 0.f;
        if (it < EE * EE) { di[cnt] = it / EE; ei[cnt] = it % EE; }
        else              { di[cnt] = it - EE * EE; ei[cnt] = -1; }
        cnt++;
    }

    for (int c0 = 0; c0 < SS / KV_SEGS; c0 += 64) {
        int n0 = n0base + c0;
        {
            int r = tid >> 2, f = (tid & 3) * 4;
            const float4 k4 = *(const float4*)(g_qkv_lin + ((size_t)(b * SS + n0 + r)) * NLIN + 256 + h * FF + f);
            sk[r][f + 0] = k4.x; sk[r][f + 1] = k4.y; sk[r][f + 2] = k4.z; sk[r][f + 3] = k4.w;
        }
        for (int i = tid; i < 64 * EE; i += 256) {
            int r = i / EE, e = i % EE;
            sv[r][e] = g_qkv_lin[((size_t)(b * SS + n0 + r)) * NLIN + 512 + h * EE + e];
        }
        __syncthreads();

        for (int u = 0; u < cnt; u++) {
            int d = di[u], e = ei[u];
            float a = acc[u];
            if (e >= 0) {
                if (d == 0) {
                    for (int nn = 0; nn < 64; nn++) a += sv[nn][e];
                } else if (d <= FF) {
                    int dd = d - 1;
                    for (int nn = 0; nn < 64; nn++) a += sk[nn][dd] * sv[nn][e];
                } else {
                    int dd = d - 1 - FF;
                    for (int nn = 0; nn < 64; nn++) { float kk = sk[nn][dd]; a += 0.5f * kk * kk * sv[nn][e]; }
                }
            } else {
                if (d == 0) {
                    a += 64.f;
                } else if (d <= FF) {
                    int dd = d - 1;
                    for (int nn = 0; nn < 64; nn++) a += sk[nn][dd];
                } else {
                    int dd = d - 1 - FF;
                    for (int nn = 0; nn < 64; nn++) { float kk = sk[nn][dd]; a += 0.5f * kk * kk; }
                }
            }
            acc[u] = a;
        }
        __syncthreads();
    }

    for (int u = 0; u < cnt; u++) {
        if (ei[u] >= 0) atomicAdd(&g_kv[((size_t)bh) * EE * EE + di[u] * EE + ei[u]], acc[u]);
        else            atomicAdd(&g_ksum[bh * EE + di[u]], acc[u]);
    }
}

// writes its result directly into g_ob concat columns [0, 528)
__global__ void lin_out_kernel(const int* __restrict__ mask)
{
    int s = blockIdx.x, b = blockIdx.y;
    __shared__ float sq[HH * FF];
    int tid = threadIdx.x;
    if (tid < HH * FF) sq[tid] = g_qkv_lin[((size_t)(b * SS + s)) * NLIN + tid];
    __syncthreads();
    if (tid >= DD) return;

    int h = tid / EE, e = tid % EE;
    const float* kv = g_kv + ((size_t)(b * HH + h)) * EE * EE;
    const float* q  = sq + h * FF;

    float qkv  = kv[e];
    float qsum = 1.f;
#pragma unroll
    for (int j = 0; j < FF; j++) {
        float qa = q[j];
        float q2 = 0.5f * qa * qa;
        qkv  += qa * kv[(1 + j) * EE + e] + q2 * kv[(1 + FF + j) * EE + e];
        qsum += qa + q2;
    }
    float z = qsum * g_ksum[(b * HH + h) * EE + e];
    float out = qkv / (z + 1e-9f);
    if (mask[b * SS + s] == 0) out = 0.f;
    store_ob3((size_t)(b * SS + s) * KP2, tid, out);
}

// ==================== tf32 MMA flash window attention =========================
// P stays in registers: PV A-operand fed directly from the QK C-fragment with a
// consistent within-8-group key permutation (k-lane t <-> key 2t, t+4 <-> 2t+1);
// V read at rows 2t/2t+1, stride 60 (conflict-free). No P smem staging.
// smem floats: Qstage 128*40 (5120) | sK 2*64*44 @5120 | sV 2*64*60 @10752 | 4 mask words @18432
#define WM_SMEM (18448*4)

__global__ void __launch_bounds__(256)
win_mma_kernel(const int* __restrict__ mask)
{
    extern __shared__ float smf[];
    unsigned* maskw = (unsigned*)(smf + 18432);

    int qt = (int)gridDim.x - 1 - (int)blockIdx.x;
    int bh = blockIdx.y; int b = bh >> 4, h = bh & 15;
    int tid = threadIdx.x, wid = tid >> 5, lane = tid & 31;
    int g = lane >> 2, t = lane & 3;
    int rw = wid * 16;
    int q0 = qt * 128;
    int kend = min(SS, q0 + 127 + WIN);
    const float scale = 0.17407765595569785f * 1.44269504088896340736f; // 1/sqrt(33)*log2(e)

    int pr[10], pd[10];
#pragma unroll
    for (int j = 0; j < 10; j++) { int i = tid + j * 256; pr[j] = i / 40; pd[j] = i - pr[j] * 40; }

    // stage Q (pre-scaled into log2 domain, tf32), stride 40; extract A fragments
    for (int i = tid; i < 128 * 40; i += 256) {
        int r = i / 40, d = i - r * 40;
        float v = (d < EE) ? g_qkv_win[((size_t)(b * SS + q0 + r)) * NWIN + h * EE + d] * scale : 0.f;
        smf[r * 40 + d] = to_tf32(v);
    }
    __syncthreads();
    uint32_t aq[5][4];
#pragma unroll
    for (int kc = 0; kc < 5; kc++) {
        aq[kc][0] = __float_as_uint(smf[(rw + g    ) * 40 + kc * 8 + t    ]);
        aq[kc][1] = __float_as_uint(smf[(rw + g + 8) * 40 + kc * 8 + t    ]);
        aq[kc][2] = __float_as_uint(smf[(rw + g    ) * 40 + kc * 8 + t + 4]);
        aq[kc][3] = __float_as_uint(smf[(rw + g + 8) * 40 + kc * 8 + t + 4]);
    }
    __syncthreads();

    float co[5][4];
#pragma unroll
    for (int n = 0; n < 5; n++)
#pragma unroll
        for (int r = 0; r < 4; r++) co[n][r] = 0.f;
    float mrun0 = -1e30f, mrun1 = -1e30f, lsum0 = 0.f, lsum1 = 0.f;

    const int T = (kend + 63) >> 6;
    float kr_[10], vr_[10]; int mk_;

    // prologue: load tile 0 into regs, stage into buffer 0
    {
        int nv = min(64, kend);
#pragma unroll
        for (int j = 0; j < 10; j++) {
            bool ok = (pr[j] < nv) && (pd[j] < EE);
            size_t rowb = ((size_t)(b * SS + pr[j])) * NWIN;
            kr_[j] = ok ? g_qkv_win[rowb + 576 + h * EE + pd[j]] : 0.f;
            vr_[j] = ok ? g_qkv_win[rowb + 1152 + h * EE + pd[j]] : 0.f;
        }
        mk_ = (tid < 64) ? ((tid < nv) ? mask[b * SS + tid] : 0) : 0;
#pragma unroll
        for (int j = 0; j < 10; j++) {
            smf[5120 + pr[j] * 44 + pd[j]]  = to_tf32(kr_[j]);
            smf[10752 + pr[j] * 60 + pd[j]] = to_tf32(vr_[j]);
        }
        if (wid < 2) {
            unsigned bal = __ballot_sync(0xffffffffu, mk_ != 0);
            if (lane == 0) maskw[wid] = bal;
        }
    }
    __syncthreads();

    for (int tt = 0; tt < T; tt++) {
        int buf = tt & 1;
        int kt = tt << 6;
        float* sK = smf + 5120  + buf * 2816;
        float* sV = smf + 10752 + buf * 3840;
        uint64_t mbits = ((uint64_t)maskw[buf * 2 + 1] << 32) | maskw[buf * 2];

        // prefetch tile tt+1 into registers
        if (tt + 1 < T) {
            int ktn = (tt + 1) << 6;
            int nv = min(64, kend - ktn);
#pragma unroll
            for (int j = 0; j < 10; j++) {
                bool ok = (pr[j] < nv) && (pd[j] < EE);
                size_t rowb = ((size_t)(b * SS + ktn + pr[j])) * NWIN;
                kr_[j] = ok ? g_qkv_win[rowb + 576 + h * EE + pd[j]] : 0.f;
                vr_[j] = ok ? g_qkv_win[rowb + 1152 + h * EE + pd[j]] : 0.f;
            }
            mk_ = (tid < 64) ? ((tid < nv) ? mask[b * SS + ktn + tid] : 0) : 0;
        }

        // --- QK^T: S[16 x 64] per warp ---
        float cs[8][4];
#pragma unroll
        for (int n = 0; n < 8; n++)
#pragma unroll
            for (int r = 0; r < 4; r++) cs[n][r] = 0.f;
#pragma unroll
        for (int kc = 0; kc < 5; kc++)
#pragma unroll
            for (int n = 0; n < 8; n++) {
                uint32_t b0 = __float_as_uint(sK[(n * 8 + g) * 44 + kc * 8 + t    ]);
                uint32_t b1 = __float_as_uint(sK[(n * 8 + g) * 44 + kc * 8 + t + 4]);
                MMA_TF32(cs[n], aq[kc][0], aq[kc][1], aq[kc][2], aq[kc][3], b0, b1);
            }

        // --- mask IN PLACE (bitmask; fast path for full tiles) ---
        if (!(mbits == ~0ull && kt <= q0)) {
            int r0g = q0 + rw + g, r1g = r0g + 8;
#pragma unroll
            for (int n = 0; n < 8; n++) {
                int c0 = n * 8 + 2 * t;
                int cg0 = kt + c0, cg1 = cg0 + 1;
                bool m0 = (mbits >> c0) & 1, m1 = (mbits >> (c0 + 1)) & 1;
                if (!(m0 && cg0 <= r0g + WIN - 1)) cs[n][0] = -1e30f;
                if (!(m1 && cg1 <= r0g + WIN - 1)) cs[n][1] = -1e30f;
                if (!(m0 && cg0 <= r1g + WIN - 1)) cs[n][2] = -1e30f;
                if (!(m1 && cg1 <= r1g + WIN - 1)) cs[n][3] = -1e30f;
            }
        }

        // --- warp-local online softmax (log2 domain), exp IN PLACE ---
        float mx0 = -1e30f, mx1 = -1e30f;
#pragma unroll
        for (int n = 0; n < 8; n++) {
            mx0 = fmaxf(mx0, fmaxf(cs[n][0], cs[n][1]));
            mx1 = fmaxf(mx1, fmaxf(cs[n][2], cs[n][3]));
        }
        mx0 = fmaxf(mx0, __shfl_xor_sync(0xffffffffu, mx0, 1));
        mx0 = fmaxf(mx0, __shfl_xor_sync(0xffffffffu, mx0, 2));
        mx1 = fmaxf(mx1, __shfl_xor_sync(0xffffffffu, mx1, 1));
        mx1 = fmaxf(mx1, __shfl_xor_sync(0xffffffffu, mx1, 2));
        float mn0 = fmaxf(mrun0, mx0), mn1 = fmaxf(mrun1, mx1);
        float fac0 = ex2f(mrun0 - mn0), fac1 = ex2f(mrun1 - mn1);
        float ps0 = 0.f, ps1 = 0.f;
#pragma unroll
        for (int n = 0; n < 8; n++) {
            cs[n][0] = ex2f(cs[n][0] - mn0); ps0 += cs[n][0];
            cs[n][1] = ex2f(cs[n][1] - mn0); ps0 += cs[n][1];
            cs[n][2] = ex2f(cs[n][2] - mn1); ps1 += cs[n][2];
            cs[n][3] = ex2f(cs[n][3] - mn1); ps1 += cs[n][3];
        }
        ps0 += __shfl_xor_sync(0xffffffffu, ps0, 1);
        ps0 += __shfl_xor_sync(0xffffffffu, ps0, 2);
        ps1 += __shfl_xor_sync(0xffffffffu, ps1, 1);
        ps1 += __shfl_xor_sync(0xffffffffu, ps1, 2);
        lsum0 = lsum0 * fac0 + ps0; mrun0 = mn0;
        lsum1 = lsum1 * fac1 + ps1; mrun1 = mn1;

        // --- rescale + P @ V, P directly from registers (keys permuted 2t/2t+1) ---
#pragma unroll
        for (int n = 0; n < 5; n++) {
            co[n][0] *= fac0; co[n][1] *= fac0; co[n][2] *= fac1; co[n][3] *= fac1;
        }
#pragma unroll
        for (int kc = 0; kc < 8; kc++) {
            uint32_t a0 = __float_as_uint(to_tf32(cs[kc][0]));  // row g,   key kc*8+2t
            uint32_t a1 = __float_as_uint(to_tf32(cs[kc][2]));  // row g+8, key kc*8+2t
            uint32_t a2 = __float_as_uint(to_tf32(cs[kc][1]));  // row g,   key kc*8+2t+1
            uint32_t a3 = __float_as_uint(to_tf32(cs[kc][3]));  // row g+8, key kc*8+2t+1
            const float* vrow0 = sV + (kc * 8 + 2 * t) * 60;
#pragma unroll
            for (int n = 0; n < 5; n++) {
                uint32_t b0 = __float_as_uint(vrow0[n * 8 + g]);
                uint32_t b1 = __float_as_uint(vrow0[60 + n * 8 + g]);
                MMA_TF32(co[n], a0, a1, a2, a3, b0, b1);
            }
        }

        // --- store prefetched tile into the other buffer ---
        if (tt + 1 < T) {
            int nb = 1 - buf;
            float* nK = smf + 5120  + nb * 2816;
            float* nV = smf + 10752 + nb * 3840;
#pragma unroll
            for (int j = 0; j < 10; j++) {
                nK[pr[j] * 44 + pd[j]] = to_tf32(kr_[j]);
                nV[pr[j] * 60 + pd[j]] = to_tf32(vr_[j]);
            }
            if (wid < 2) {
                unsigned bal = __ballot_sync(0xffffffffu, mk_ != 0);
                if (lane == 0) maskw[nb * 2 + wid] = bal;
            }
        }
        __syncthreads();
    }

    float inv0 = 1.f / lsum0, inv1 = 1.f / lsum1;
    int r0 = q0 + rw + g, r1 = r0 + 8;
    size_t base0 = (size_t)(b * SS + r0) * KP2;
    size_t base1 = (size_t)(b * SS + r1) * KP2;
    int colbase = DD + h * EE;
#pragma unroll
    for (int n = 0; n < 5; n++) {
        int c0 = n * 8 + 2 * t;
        if (c0 < EE) {
            store_ob3(base0, colbase + c0, co[n][0] * inv0);
            store_ob3(base1, colbase + c0, co[n][2] * inv1);
        }
        if (c0 + 1 < EE) {
            store_ob3(base0, colbase + c0 + 1, co[n][1] * inv0);
            store_ob3(base1, colbase + c0 + 1, co[n][3] * inv1);
        }
    }
}

// ==================== launcher ================================================
extern "C" void kernel_launch(void* const* d_in, const int* in_sizes, int n_in,
                              void* d_out, int out_size)
{
    const float* x      = (const float*)d_in[0];
    const int*   mask   = (const int*)  d_in[1];
    const float* Wq_lin = (const float*)d_in[2];
    const float* Wk_lin = (const float*)d_in[3];
    const float* Wv_lin = (const float*)d_in[4];
    const float* Wo_lin = (const float*)d_in[5];
    const float* Wq_win = (const float*)d_in[6];
    const float* Wk_win = (const float*)d_in[7];
    const float* Wv_win = (const float*)d_in[8];
    const float* Wo_win = (const float*)d_in[9];
    float* out = (float*)d_out;

    float *p_qkv_lin, *p_qkv_win, *p_wlinb;
    __nv_bfloat16 *p_xb, *p_ob, *p_wwinb, *p_wob;
    cudaGetSymbolAddress((void**)&p_qkv_lin, g_qkv_lin);
    cudaGetSymbolAddress((void**)&p_qkv_win, g_qkv_win);
    cudaGetSymbolAddress((void**)&p_wlinb,   g_wlinb);
    cudaGetSymbolAddress((void**)&p_xb,   g_xb);
    cudaGetSymbolAddress((void**)&p_ob,   g_ob);
    cudaGetSymbolAddress((void**)&p_wwinb, g_wwinb);
    cudaGetSymbolAddress((void**)&p_wob,  g_wob);

    static cudaStream_t s_win = 0;
    static cudaEvent_t  evFork = 0, evJoin = 0;
    if (s_win == 0) {
        cudaStreamCreateWithFlags(&s_win, cudaStreamNonBlocking);
        cudaEventCreateWithFlags(&evFork, cudaEventDisableTiming);
        cudaEventCreateWithFlags(&evJoin, cudaEventDisableTiming);
        cudaFuncSetAttribute(win_mma_kernel, cudaFuncAttributeMaxDynamicSharedMemorySize, WM_SMEM);
    }

    // -------- fork win chain off the capture stream --------
    cudaEventRecord(evFork, 0);
    cudaStreamWaitEvent(s_win, evFork, 0);

    // win chain (s_win): splits -> merged HMMA projection -> tf32 flash attn
    split_x_kernel<<<(MTOT*KP1 + 255)/256, 256, 0, s_win>>>(x);
    split_wwin_kernel<<<dim3(KP1/32, NWIN/32), dim3(32, 8), 0, s_win>>>(Wq_win, Wk_win, Wv_win);
    gemm_mma_kernel<<<dim3(NWIN/64, MTOT/128), 256, 0, s_win>>>(p_xb, p_wwinb, p_qkv_win, KP1, NWIN);
    win_mma_kernel<<<dim3(SS/128, BB*HH), 256, WM_SMEM, s_win>>>(mask);

    // lin chain (capture stream): wo split + merged fp32 projection -> linear attn
    split_wo_kernel<<<dim3(KP2/32, NP_D/32), dim3(32, 8)>>>(Wo_lin, Wo_win);
    concat_wlin_kernel<<<(DD*NLIN + 255)/256, 256>>>(Wq_lin, Wk_lin, Wv_lin);
    gemm_lin_kernel<<<dim3((NLIN + LN - 1)/LN, MTOT/LM), 256>>>(x, p_wlinb, p_qkv_lin, MTOT, NLIN, DD);
    clear_kv_kernel<<<(BB*HH*EE*EE + 255)/256, 256>>>();
    lin_kv_kernel<<<dim3(BB*HH, KV_SEGS), 256>>>();
    lin_out_kernel<<<dim3(SS, BB), 544>>>(mask);

    // -------- join, then fused output projection --------
    cudaEventRecord(evJoin, s_win);
    cudaStreamWaitEvent(0, evJoin, 0);
    gemm_mma_kernel<<<dim3(NP_D/64, MTOT/128), 256>>>(p_ob, p_wob, out, KP2, DD);
}